// round 8
// baseline (speedup 1.0000x reference)
#include <cuda_runtime.h>
#include <cuda_bf16.h>
#include <cstdint>

#define BATCH 2
#define SEQ   2048
#define HID   2048
#define NH    32
#define NG    8
#define HD    64
#define KVD   (NG*HD)     // 512
#define MTOT  (BATCH*SEQ) // 4096
#define NC    (HID + 2*KVD)  // 3072 combined QKV cols
#define GRID_P 296           // persistent grid: 148 SMs x 2 CTAs

typedef __nv_bfloat16 bf16;

// ---------------- device scratch (no allocation allowed) ----------------
__device__ bf16 g_xh[(size_t)MTOT*HID],  g_xl[(size_t)MTOT*HID];
__device__ bf16 g_wch[(size_t)HID*NC],   g_wcl[(size_t)HID*NC];   // [K, Q|K|V]
__device__ bf16 g_woh[(size_t)HID*HID],  g_wol[(size_t)HID*HID];  // [K,N]
__device__ bf16 g_qh[(size_t)BATCH*NH*SEQ*HD], g_ql[(size_t)BATCH*NH*SEQ*HD];
__device__ bf16 g_kh[(size_t)BATCH*NG*SEQ*HD], g_kl[(size_t)BATCH*NG*SEQ*HD];
__device__ bf16 g_vh[(size_t)BATCH*NG*HD*SEQ], g_vl[(size_t)BATCH*NG*HD*SEQ]; // [b,g,d,s]
__device__ bf16 g_oh[(size_t)MTOT*HID],  g_ol[(size_t)MTOT*HID];

// ---------------- helpers ----------------
__device__ __forceinline__ void split2(float x0, float x1, uint32_t& h, uint32_t& l) {
    __nv_bfloat162 hb = __floats2bfloat162_rn(x0, x1);
    const float r0 = x0 - __bfloat162float(hb.x);
    const float r1 = x1 - __bfloat162float(hb.y);
    __nv_bfloat162 lb = __floats2bfloat162_rn(r0, r1);
    h = *reinterpret_cast<uint32_t*>(&hb);
    l = *reinterpret_cast<uint32_t*>(&lb);
}

__device__ __forceinline__ void mma_bf16(float d[4], const uint32_t a[4],
                                         uint32_t b0, uint32_t b1) {
    asm volatile(
        "mma.sync.aligned.m16n8k16.row.col.f32.bf16.bf16.f32 "
        "{%0,%1,%2,%3}, {%4,%5,%6,%7}, {%8,%9}, {%0,%1,%2,%3};\n"
        : "+f"(d[0]), "+f"(d[1]), "+f"(d[2]), "+f"(d[3])
        : "r"(a[0]), "r"(a[1]), "r"(a[2]), "r"(a[3]), "r"(b0), "r"(b1));
}

__device__ __forceinline__ void ldsm4(uint32_t& r0, uint32_t& r1, uint32_t& r2,
                                      uint32_t& r3, uint32_t addr) {
    asm volatile("ldmatrix.sync.aligned.m8n8.x4.shared.b16 {%0,%1,%2,%3}, [%4];"
                 : "=r"(r0), "=r"(r1), "=r"(r2), "=r"(r3) : "r"(addr));
}
__device__ __forceinline__ void ldsm4t(uint32_t& r0, uint32_t& r1, uint32_t& r2,
                                       uint32_t& r3, uint32_t addr) {
    asm volatile("ldmatrix.sync.aligned.m8n8.x4.trans.shared.b16 {%0,%1,%2,%3}, [%4];"
                 : "=r"(r0), "=r"(r1), "=r"(r2), "=r"(r3) : "r"(addr));
}

__device__ __forceinline__ void cp16(uint32_t saddr, const void* gaddr) {
    asm volatile("cp.async.cg.shared.global [%0], [%1], 16;"
                 :: "r"(saddr), "l"(gaddr) : "memory");
}
#define CP_COMMIT() asm volatile("cp.async.commit_group;" ::: "memory")
#define CP_WAIT0()  asm volatile("cp.async.wait_group 0;"  ::: "memory")

// ---------------- fp32 -> bf16 hi/lo converts ----------------
__global__ __launch_bounds__(256) void convert_kernel(
    const float* __restrict__ src, bf16* __restrict__ h, bf16* __restrict__ l, int n4)
{
    const int i = blockIdx.x * blockDim.x + threadIdx.x;
    if (i >= n4) return;
    float4 v = reinterpret_cast<const float4*>(src)[i];
    uint32_t h0, l0, h1, l1;
    split2(v.x, v.y, h0, l0);
    split2(v.z, v.w, h1, l1);
    reinterpret_cast<uint32_t*>(h)[i * 2]     = h0;
    reinterpret_cast<uint32_t*>(h)[i * 2 + 1] = h1;
    reinterpret_cast<uint32_t*>(l)[i * 2]     = l0;
    reinterpret_cast<uint32_t*>(l)[i * 2 + 1] = l1;
}

// W [2048, Nsrc] fp32 -> combined [2048, NC] bf16 hi/lo at column offset
__global__ __launch_bounds__(256) void convW_kernel(
    const float* __restrict__ src, bf16* __restrict__ h, bf16* __restrict__ l,
    int Nsrc, int colOff, int n4)
{
    const int i = blockIdx.x * blockDim.x + threadIdx.x;
    if (i >= n4) return;
    const int perRow = Nsrc >> 2;
    const int k = i / perRow;
    const int c4 = (i - k * perRow) * 4;
    float4 v = reinterpret_cast<const float4*>(src)[i];
    uint32_t h0, l0, h1, l1;
    split2(v.x, v.y, h0, l0);
    split2(v.z, v.w, h1, l1);
    const size_t o = ((size_t)k * NC + colOff + c4) >> 1;  // uint32 index
    reinterpret_cast<uint32_t*>(h)[o]     = h0;
    reinterpret_cast<uint32_t*>(h)[o + 1] = h1;
    reinterpret_cast<uint32_t*>(l)[o]     = l0;
    reinterpret_cast<uint32_t*>(l)[o + 1] = l1;
}

// ---------------------------------------------------------------------------
// 3x-bf16 GEMM, persistent CTAs. CTA tile 128x128, BK=32, 256 threads
// (8 warps 4x2, warp tile 32x64), cp.async double buffer + ldmatrix.
// MODE 0: fp32 +bias -> Cf (O projection)
// MODE 4: combined QKV epilogue -> scatter into g_q*/g_k*/g_v* by n region
// K epilogue is scaled by 0.125*log2(e) so softmax can use exp2.
// ---------------------------------------------------------------------------
#define GAP 40     // A smem pitch (bf16)
#define GBP 136    // B smem pitch (bf16)
#define GA_BYTES (128 * GAP * 2)            // 10240
#define GB_BYTES (32 * GBP * 2)             // 8704
#define GSTAGE   (2 * GA_BYTES + 2 * GB_BYTES)   // 37888
#define GEMM_SMEM (2 * GSTAGE)                   // 75776
#define KSCALE (0.125f * 1.44269504088896f)

template<int MODE>
__global__ __launch_bounds__(256, 2) void gemm_kernel(
    const bf16* __restrict__ Ah, const bf16* __restrict__ Al,
    const bf16* __restrict__ Bh, const bf16* __restrict__ Bl,
    const float* __restrict__ bias0, const float* __restrict__ bias1,
    const float* __restrict__ bias2,
    float* __restrict__ Cf, int M, int N, int K)
{
    extern __shared__ char smc[];
    const uint32_t sbase = (uint32_t)__cvta_generic_to_shared(smc);

    const int tid  = threadIdx.x;
    const int lane = tid & 31;
    const int wid  = tid >> 5;
    const int g = lane >> 2, c = lane & 3;
    const int quad = lane >> 3, r8 = lane & 7;
    const int wm0 = (wid & 3) * 32;
    const int wn0 = (wid >> 2) * 64;
    const int arow = (quad & 1) * 8 + r8;
    const int acol = (quad >> 1) * 8;
    const int NT = K / 32;
    const int ntx = N / 128;
    const int numTiles = ntx * (M / 128);

    for (int vt = blockIdx.x; vt < numTiles; vt += gridDim.x) {
        const int row0 = (vt / ntx) * 128;
        const int col0 = (vt - (vt / ntx) * ntx) * 128;

        float acc[2][8][4];
        #pragma unroll
        for (int mt = 0; mt < 2; mt++)
            #pragma unroll
            for (int nt = 0; nt < 8; nt++)
                #pragma unroll
                for (int j = 0; j < 4; j++) acc[mt][nt][j] = 0.0f;

        auto fill = [&](int kt, int st) {
            const int k0 = kt * 32;
            const uint32_t s0 = sbase + st * GSTAGE;
            #pragma unroll
            for (int i = 0; i < 2; i++) {
                const int idx = tid + i * 256;
                const int r = idx >> 2, q = (idx & 3) * 8;
                const size_t go = (size_t)(row0 + r) * K + k0 + q;
                cp16(s0 + (r * GAP + q) * 2,            Ah + go);
                cp16(s0 + GA_BYTES + (r * GAP + q) * 2, Al + go);
            }
            #pragma unroll
            for (int i = 0; i < 2; i++) {
                const int idx = tid + i * 256;
                const int r = idx >> 4, q = (idx & 15) * 8;
                const size_t go = (size_t)(k0 + r) * N + col0 + q;
                cp16(s0 + 2 * GA_BYTES + (r * GBP + q) * 2,            Bh + go);
                cp16(s0 + 2 * GA_BYTES + GB_BYTES + (r * GBP + q) * 2, Bl + go);
            }
        };

        fill(0, 0); CP_COMMIT();

        for (int kt = 0; kt < NT; kt++) {
            CP_WAIT0();
            __syncthreads();
            if (kt + 1 < NT) { fill(kt + 1, (kt + 1) & 1); CP_COMMIT(); }
            const uint32_t s0 = sbase + (kt & 1) * GSTAGE;

            #pragma unroll
            for (int kk = 0; kk < 2; kk++) {
                uint32_t ah[2][4], al[2][4];
                #pragma unroll
                for (int mt = 0; mt < 2; mt++) {
                    const uint32_t aaddr =
                        s0 + ((wm0 + mt * 16 + arow) * GAP + kk * 16 + acol) * 2;
                    ldsm4(ah[mt][0], ah[mt][1], ah[mt][2], ah[mt][3], aaddr);
                    ldsm4(al[mt][0], al[mt][1], al[mt][2], al[mt][3], aaddr + GA_BYTES);
                }
                #pragma unroll
                for (int np = 0; np < 4; np++) {
                    const uint32_t baddr = s0 + 2 * GA_BYTES +
                        ((kk * 16 + arow) * GBP + wn0 + np * 16 + acol) * 2;
                    uint32_t bh0, bh1, bh2, bh3, bl0, bl1, bl2, bl3;
                    ldsm4t(bh0, bh1, bh2, bh3, baddr);
                    ldsm4t(bl0, bl1, bl2, bl3, baddr + GB_BYTES);
                    #pragma unroll
                    for (int mt = 0; mt < 2; mt++) {
                        mma_bf16(acc[mt][2*np],   al[mt], bh0, bh1);
                        mma_bf16(acc[mt][2*np],   ah[mt], bl0, bl1);
                        mma_bf16(acc[mt][2*np],   ah[mt], bh0, bh1);
                        mma_bf16(acc[mt][2*np+1], al[mt], bh2, bh3);
                        mma_bf16(acc[mt][2*np+1], ah[mt], bl2, bl3);
                        mma_bf16(acc[mt][2*np+1], ah[mt], bh2, bh3);
                    }
                }
            }
        }

        // ---- epilogue ----
        #pragma unroll
        for (int mt = 0; mt < 2; mt++) {
            const int r = row0 + wm0 + mt * 16 + g;     // and r+8
            const int b0 = r >> 11, s0i = r & 2047;
            const int b1 = (r + 8) >> 11, s1i = (r + 8) & 2047;
            #pragma unroll
            for (int nt = 0; nt < 8; nt++) {
                const int n = col0 + wn0 + nt * 8 + 2 * c;
                if (MODE == 0) {
                    const float bv0 = bias0[n], bv1 = bias0[n + 1];
                    const float v0 = acc[mt][nt][0] + bv0;
                    const float v1 = acc[mt][nt][1] + bv1;
                    const float v2 = acc[mt][nt][2] + bv0;
                    const float v3 = acc[mt][nt][3] + bv1;
                    *(float2*)(Cf + (size_t)r * N + n)       = make_float2(v0, v1);
                    *(float2*)(Cf + (size_t)(r + 8) * N + n) = make_float2(v2, v3);
                } else {
                    if (n < HID) {               // ---- Q: [b,h,s,d] ----
                        const float bv0 = bias0[n], bv1 = bias0[n + 1];
                        const float v0 = acc[mt][nt][0] + bv0;
                        const float v1 = acc[mt][nt][1] + bv1;
                        const float v2 = acc[mt][nt][2] + bv0;
                        const float v3 = acc[mt][nt][3] + bv1;
                        const int hh = n >> 6, d = n & 63;
                        uint32_t ph, pl;
                        split2(v0, v1, ph, pl);
                        size_t o0 = (((size_t)(b0 * NH + hh)) * SEQ + s0i) * HD + d;
                        *reinterpret_cast<uint32_t*>(g_qh + o0) = ph;
                        *reinterpret_cast<uint32_t*>(g_ql + o0) = pl;
                        split2(v2, v3, ph, pl);
                        size_t o1 = (((size_t)(b1 * NH + hh)) * SEQ + s1i) * HD + d;
                        *reinterpret_cast<uint32_t*>(g_qh + o1) = ph;
                        *reinterpret_cast<uint32_t*>(g_ql + o1) = pl;
                    } else if (n < HID + KVD) {  // ---- K: [b,g,s,d], xKSCALE ----
                        const int nn = n - HID;
                        const float bv0 = bias1[nn], bv1 = bias1[nn + 1];
                        const float v0 = (acc[mt][nt][0] + bv0) * KSCALE;
                        const float v1 = (acc[mt][nt][1] + bv1) * KSCALE;
                        const float v2 = (acc[mt][nt][2] + bv0) * KSCALE;
                        const float v3 = (acc[mt][nt][3] + bv1) * KSCALE;
                        const int gg = nn >> 6, d = nn & 63;
                        uint32_t ph, pl;
                        split2(v0, v1, ph, pl);
                        size_t o0 = (((size_t)(b0 * NG + gg)) * SEQ + s0i) * HD + d;
                        *reinterpret_cast<uint32_t*>(g_kh + o0) = ph;
                        *reinterpret_cast<uint32_t*>(g_kl + o0) = pl;
                        split2(v2, v3, ph, pl);
                        size_t o1 = (((size_t)(b1 * NG + gg)) * SEQ + s1i) * HD + d;
                        *reinterpret_cast<uint32_t*>(g_kh + o1) = ph;
                        *reinterpret_cast<uint32_t*>(g_kl + o1) = pl;
                    } else {                     // ---- V: transposed [b,g,d,s] ----
                        const int nn = n - HID - KVD;
                        const float bv0 = bias2[nn], bv1 = bias2[nn + 1];
                        const float vals[4] = {
                            acc[mt][nt][0] + bv0, acc[mt][nt][1] + bv1,
                            acc[mt][nt][2] + bv0, acc[mt][nt][3] + bv1 };
                        const int gg = nn >> 6, d = nn & 63;
                        const size_t base0 = ((size_t)(b0 * NG + gg)) * HD;
                        const size_t base1 = ((size_t)(b1 * NG + gg)) * HD;
                        const size_t offs[4] = {
                            (base0 + d) * SEQ + s0i, (base0 + d + 1) * SEQ + s0i,
                            (base1 + d) * SEQ + s1i, (base1 + d + 1) * SEQ + s1i };
                        #pragma unroll
                        for (int j = 0; j < 4; j++) {
                            const bf16 hb = __float2bfloat16(vals[j]);
                            const bf16 lb = __float2bfloat16(vals[j] - __bfloat162float(hb));
                            g_vh[offs[j]] = hb;
                            g_vl[offs[j]] = lb;
                        }
                    }
                }
            }
        }
    }
}

// ---------------------------------------------------------------------------
// Flash attention, persistent CTAs. 3x-bf16 mma, pre-split operands,
// ldmatrix fragments, P in registers, cp.async double-buffered K/V,
// exp2-based online softmax (log2e folded into K projection).
// ---------------------------------------------------------------------------
#define AKP 72
#define AK_BYTES (64 * AKP * 2)
#define ASTAGE   (4 * AK_BYTES)
#define ATTN_SMEM (2 * ASTAGE)

__global__ __launch_bounds__(256, 2) void attn_kernel(
    const bf16* __restrict__ Qh, const bf16* __restrict__ Ql,
    const bf16* __restrict__ Kh, const bf16* __restrict__ Kl,
    const bf16* __restrict__ Vh, const bf16* __restrict__ Vl,
    bf16* __restrict__ Oh, bf16* __restrict__ Ol)
{
    extern __shared__ char smc[];
    const uint32_t sbase = (uint32_t)__cvta_generic_to_shared(smc);

    const int tid  = threadIdx.x;
    const int lane = tid & 31;
    const int wid  = tid >> 5;
    const int g = lane >> 2, c = lane & 3;
    const int quad = lane >> 3, r8 = lane & 7;
    const int wr0 = wid * 16;
    const int lrow = (quad >> 1) * 8 + r8;
    const int lcol = (quad & 1) * 8;

    const int numV = (SEQ / 128) * NH * BATCH;   // 1024

    for (int v = blockIdx.x; v < numV; v += gridDim.x) {
        const int qt = v & 15;
        const int h  = (v >> 4) & 31;
        const int b  = v >> 9;
        const int gh = h >> 2;

        const size_t koff = ((size_t)(b * NG + gh)) * SEQ * HD;
        const size_t voff = ((size_t)(b * NG + gh)) * HD * SEQ;

        const bf16* qbh = Qh + (((size_t)(b * NH + h)) * SEQ + qt * 128 + wr0) * HD;
        const bf16* qbl = Ql + (((size_t)(b * NH + h)) * SEQ + qt * 128 + wr0) * HD;
        uint32_t qh[4][4], ql[4][4];
        #pragma unroll
        for (int kt = 0; kt < 4; kt++) {
            const int o0 = g * HD + kt * 16 + 2 * c;
            qh[kt][0] = *(const uint32_t*)(qbh + o0);
            qh[kt][1] = *(const uint32_t*)(qbh + o0 + 8 * HD);
            qh[kt][2] = *(const uint32_t*)(qbh + o0 + 8);
            qh[kt][3] = *(const uint32_t*)(qbh + o0 + 8 * HD + 8);
            ql[kt][0] = *(const uint32_t*)(qbl + o0);
            ql[kt][1] = *(const uint32_t*)(qbl + o0 + 8 * HD);
            ql[kt][2] = *(const uint32_t*)(qbl + o0 + 8);
            ql[kt][3] = *(const uint32_t*)(qbl + o0 + 8 * HD + 8);
        }

        auto fill = [&](int t, int st) {
            const uint32_t s0 = sbase + st * ASTAGE;
            #pragma unroll
            for (int i = 0; i < 2; i++) {
                const int idx = tid + i * 256;
                const int r = idx >> 3, q = (idx & 7) * 8;
                const uint32_t so = (r * AKP + q) * 2;
                const size_t gk = koff + (size_t)(t * 64 + r) * HD + q;
                cp16(s0 + so,            Kh + gk);
                cp16(s0 + AK_BYTES + so, Kl + gk);
                const size_t gv = voff + (size_t)r * SEQ + t * 64 + q;
                cp16(s0 + 2 * AK_BYTES + so, Vh + gv);
                cp16(s0 + 3 * AK_BYTES + so, Vl + gv);
            }
        };

        float m0 = -1e30f, m1 = -1e30f, l0 = 0.0f, l1 = 0.0f;
        float oacc[8][4];
        #pragma unroll
        for (int nt = 0; nt < 8; nt++)
            #pragma unroll
            for (int j = 0; j < 4; j++) oacc[nt][j] = 0.0f;

        fill(0, 0); CP_COMMIT();

        for (int t = 0; t < SEQ / 64; t++) {
            CP_WAIT0();
            __syncthreads();
            if (t + 1 < SEQ / 64) { fill(t + 1, (t + 1) & 1); CP_COMMIT(); }
            const uint32_t sK = sbase + (t & 1) * ASTAGE;
            const uint32_t sV = sK + 2 * AK_BYTES;

            float sv[8][4];
            #pragma unroll
            for (int nt = 0; nt < 8; nt++)
                #pragma unroll
                for (int j = 0; j < 4; j++) sv[nt][j] = 0.0f;

            #pragma unroll
            for (int np = 0; np < 4; np++) {
                #pragma unroll
                for (int kt = 0; kt < 4; kt++) {
                    const uint32_t ka = sK + ((np * 16 + lrow) * AKP + kt * 16 + lcol) * 2;
                    uint32_t h0, h1, h2, h3, lo0, lo1, lo2, lo3;
                    ldsm4(h0, h1, h2, h3, ka);
                    ldsm4(lo0, lo1, lo2, lo3, ka + AK_BYTES);
                    mma_bf16(sv[2*np],   ql[kt], h0, h1);
                    mma_bf16(sv[2*np],   qh[kt], lo0, lo1);
                    mma_bf16(sv[2*np],   qh[kt], h0, h1);
                    mma_bf16(sv[2*np+1], ql[kt], h2, h3);
                    mma_bf16(sv[2*np+1], qh[kt], lo2, lo3);
                    mma_bf16(sv[2*np+1], qh[kt], h2, h3);
                }
            }

            float mx0 = -1e30f, mx1 = -1e30f;
            #pragma unroll
            for (int nt = 0; nt < 8; nt++) {
                mx0 = fmaxf(mx0, fmaxf(sv[nt][0], sv[nt][1]));
                mx1 = fmaxf(mx1, fmaxf(sv[nt][2], sv[nt][3]));
            }
            mx0 = fmaxf(mx0, __shfl_xor_sync(0xffffffffu, mx0, 1));
            mx0 = fmaxf(mx0, __shfl_xor_sync(0xffffffffu, mx0, 2));
            mx1 = fmaxf(mx1, __shfl_xor_sync(0xffffffffu, mx1, 1));
            mx1 = fmaxf(mx1, __shfl_xor_sync(0xffffffffu, mx1, 2));

            const float nm0 = fmaxf(m0, mx0), nm1 = fmaxf(m1, mx1);
            const float corr0 = exp2f(m0 - nm0), corr1 = exp2f(m1 - nm1);
            float ls0 = 0.0f, ls1 = 0.0f;
            #pragma unroll
            for (int nt = 0; nt < 8; nt++) {
                sv[nt][0] = exp2f(sv[nt][0] - nm0);
                sv[nt][1] = exp2f(sv[nt][1] - nm0);
                sv[nt][2] = exp2f(sv[nt][2] - nm1);
                sv[nt][3] = exp2f(sv[nt][3] - nm1);
                ls0 += sv[nt][0] + sv[nt][1];
                ls1 += sv[nt][2] + sv[nt][3];
            }
            ls0 += __shfl_xor_sync(0xffffffffu, ls0, 1);
            ls0 += __shfl_xor_sync(0xffffffffu, ls0, 2);
            ls1 += __shfl_xor_sync(0xffffffffu, ls1, 1);
            ls1 += __shfl_xor_sync(0xffffffffu, ls1, 2);
            l0 = l0 * corr0 + ls0; m0 = nm0;
            l1 = l1 * corr1 + ls1; m1 = nm1;
            #pragma unroll
            for (int nt = 0; nt < 8; nt++) {
                oacc[nt][0] *= corr0; oacc[nt][1] *= corr0;
                oacc[nt][2] *= corr1; oacc[nt][3] *= corr1;
            }

            #pragma unroll
            for (int kt = 0; kt < 4; kt++) {
                uint32_t ph[4], pl[4];
                split2(sv[2*kt][0],   sv[2*kt][1],   ph[0], pl[0]);
                split2(sv[2*kt][2],   sv[2*kt][3],   ph[1], pl[1]);
                split2(sv[2*kt+1][0], sv[2*kt+1][1], ph[2], pl[2]);
                split2(sv[2*kt+1][2], sv[2*kt+1][3], ph[3], pl[3]);
                #pragma unroll
                for (int np = 0; np < 4; np++) {
                    const uint32_t va = sV + ((np * 16 + lrow) * AKP + kt * 16 + lcol) * 2;
                    uint32_t h0, h1, h2, h3, lo0, lo1, lo2, lo3;
                    ldsm4(h0, h1, h2, h3, va);
                    ldsm4(lo0, lo1, lo2, lo3, va + AK_BYTES);
                    mma_bf16(oacc[2*np],   pl, h0, h1);
                    mma_bf16(oacc[2*np],   ph, lo0, lo1);
                    mma_bf16(oacc[2*np],   ph, h0, h1);
                    mma_bf16(oacc[2*np+1], pl, h2, h3);
                    mma_bf16(oacc[2*np+1], ph, lo2, lo3);
                    mma_bf16(oacc[2*np+1], ph, h2, h3);
                }
            }
        }

        const float inv0 = 1.0f / l0, inv1 = 1.0f / l1;
        const int s0 = qt * 128 + wr0 + g;
        const size_t ob0 = ((size_t)b * SEQ + s0) * HID + h * HD;
        const size_t ob1 = ((size_t)b * SEQ + s0 + 8) * HID + h * HD;
        #pragma unroll
        for (int nt = 0; nt < 8; nt++) {
            const int d = nt * 8 + 2 * c;
            uint32_t ph, pl;
            split2(oacc[nt][0] * inv0, oacc[nt][1] * inv0, ph, pl);
            *reinterpret_cast<uint32_t*>(Oh + ob0 + d) = ph;
            *reinterpret_cast<uint32_t*>(Ol + ob0 + d) = pl;
            split2(oacc[nt][2] * inv1, oacc[nt][3] * inv1, ph, pl);
            *reinterpret_cast<uint32_t*>(Oh + ob1 + d) = ph;
            *reinterpret_cast<uint32_t*>(Ol + ob1 + d) = pl;
        }
    }
}

// ---------------------------------------------------------------------------
extern "C" void kernel_launch(void* const* d_in, const int* in_sizes, int n_in,
                              void* d_out, int out_size)
{
    const float* X  = (const float*)d_in[0];
    const float* Wq = (const float*)d_in[1];
    const float* bq = (const float*)d_in[2];
    const float* Wk = (const float*)d_in[3];
    const float* bk = (const float*)d_in[4];
    const float* Wv = (const float*)d_in[5];
    const float* bv = (const float*)d_in[6];
    const float* Wo = (const float*)d_in[7];
    const float* bo = (const float*)d_in[8];
    float* out = (float*)d_out;

    bf16 *xh, *xl, *wch, *wcl, *woh, *wol;
    bf16 *qh, *ql, *kh, *kl, *vh, *vl, *oh, *ol;
    cudaGetSymbolAddress((void**)&xh,  g_xh);  cudaGetSymbolAddress((void**)&xl,  g_xl);
    cudaGetSymbolAddress((void**)&wch, g_wch); cudaGetSymbolAddress((void**)&wcl, g_wcl);
    cudaGetSymbolAddress((void**)&woh, g_woh); cudaGetSymbolAddress((void**)&wol, g_wol);
    cudaGetSymbolAddress((void**)&qh,  g_qh);  cudaGetSymbolAddress((void**)&ql,  g_ql);
    cudaGetSymbolAddress((void**)&kh,  g_kh);  cudaGetSymbolAddress((void**)&kl,  g_kl);
    cudaGetSymbolAddress((void**)&vh,  g_vh);  cudaGetSymbolAddress((void**)&vl,  g_vl);
    cudaGetSymbolAddress((void**)&oh,  g_oh);  cudaGetSymbolAddress((void**)&ol,  g_ol);

    cudaFuncSetAttribute(gemm_kernel<0>, cudaFuncAttributeMaxDynamicSharedMemorySize, GEMM_SMEM);
    cudaFuncSetAttribute(gemm_kernel<4>, cudaFuncAttributeMaxDynamicSharedMemorySize, GEMM_SMEM);
    cudaFuncSetAttribute(attn_kernel, cudaFuncAttributeMaxDynamicSharedMemorySize, ATTN_SMEM);

    // ---- converts ----
    {
        const int n4 = MTOT * HID / 4;
        convert_kernel<<<(n4 + 255) / 256, 256>>>(X, xh, xl, n4);
    }
    {   // Wq/Wk/Wv -> combined [2048, 3072]
        int n4q = HID * HID / 4;
        convW_kernel<<<(n4q + 255) / 256, 256>>>(Wq, wch, wcl, HID, 0, n4q);
        int n4k = HID * KVD / 4;
        convW_kernel<<<(n4k + 255) / 256, 256>>>(Wk, wch, wcl, KVD, HID, n4k);
        convW_kernel<<<(n4k + 255) / 256, 256>>>(Wv, wch, wcl, KVD, HID + KVD, n4k);
    }
    {
        const int n4 = HID * HID / 4;
        convert_kernel<<<(n4 + 255) / 256, 256>>>(Wo, woh, wol, n4);
    }

    dim3 blk(256);
    // Fused QKV projection (persistent): [4096,2048] @ [2048,3072]
    gemm_kernel<4><<<GRID_P, blk, GEMM_SMEM>>>(
        xh, xl, wch, wcl, bq, bk, bv, nullptr, MTOT, NC, HID);
    // Attention (persistent) -> bf16 hi/lo [b,s,h*d]
    attn_kernel<<<GRID_P, blk, ATTN_SMEM>>>(
        qh, ql, kh, kl, vh, vl, oh, ol);
    // Output projection (persistent) -> fp32 d_out
    gemm_kernel<0><<<GRID_P, blk, GEMM_SMEM>>>(
        oh, ol, woh, wol, bo, nullptr, nullptr, out, MTOT, HID, HID);
}

// round 9
// speedup vs baseline: 1.4620x; 1.4620x over previous
#include <cuda_runtime.h>
#include <cuda_fp16.h>
#include <cstdint>

#define BATCH 2
#define SEQ   2048
#define HID   2048
#define NH    32
#define NG    8
#define HD    64
#define KVD   (NG*HD)     // 512
#define MTOT  (BATCH*SEQ) // 4096
#define NC    (HID + 2*KVD)  // 3072 combined QKV cols

typedef __half fp16;

// ---------------- device scratch (no allocation allowed) ----------------
__device__ fp16 g_xh[(size_t)MTOT*HID],  g_xl[(size_t)MTOT*HID];
__device__ fp16 g_wch[(size_t)HID*NC];                            // [K, Q|K|V] hi only
__device__ fp16 g_woh[(size_t)HID*HID];                           // [K,N] hi only
__device__ fp16 g_qh[(size_t)BATCH*NH*SEQ*HD], g_ql[(size_t)BATCH*NH*SEQ*HD];
__device__ fp16 g_kh[(size_t)BATCH*NG*SEQ*HD];                    // hi only
__device__ fp16 g_vh[(size_t)BATCH*NG*HD*SEQ];                    // [b,g,d,s] hi only
__device__ fp16 g_oh[(size_t)MTOT*HID],  g_ol[(size_t)MTOT*HID];

// ---------------- helpers ----------------
__device__ __forceinline__ void split2h(float x0, float x1, uint32_t& h, uint32_t& l) {
    __half2 hb = __floats2half2_rn(x0, x1);
    const float r0 = x0 - __half2float(__low2half(hb));
    const float r1 = x1 - __half2float(__high2half(hb));
    __half2 lb = __floats2half2_rn(r0, r1);
    h = *reinterpret_cast<uint32_t*>(&hb);
    l = *reinterpret_cast<uint32_t*>(&lb);
}
__device__ __forceinline__ uint32_t pack2h(float x0, float x1) {
    __half2 hb = __floats2half2_rn(x0, x1);
    return *reinterpret_cast<uint32_t*>(&hb);
}

__device__ __forceinline__ void mma_f16(float d[4], const uint32_t a[4],
                                        uint32_t b0, uint32_t b1) {
    asm volatile(
        "mma.sync.aligned.m16n8k16.row.col.f32.f16.f16.f32 "
        "{%0,%1,%2,%3}, {%4,%5,%6,%7}, {%8,%9}, {%0,%1,%2,%3};\n"
        : "+f"(d[0]), "+f"(d[1]), "+f"(d[2]), "+f"(d[3])
        : "r"(a[0]), "r"(a[1]), "r"(a[2]), "r"(a[3]), "r"(b0), "r"(b1));
}

__device__ __forceinline__ void ldsm4(uint32_t& r0, uint32_t& r1, uint32_t& r2,
                                      uint32_t& r3, uint32_t addr) {
    asm volatile("ldmatrix.sync.aligned.m8n8.x4.shared.b16 {%0,%1,%2,%3}, [%4];"
                 : "=r"(r0), "=r"(r1), "=r"(r2), "=r"(r3) : "r"(addr));
}
__device__ __forceinline__ void ldsm4t(uint32_t& r0, uint32_t& r1, uint32_t& r2,
                                       uint32_t& r3, uint32_t addr) {
    asm volatile("ldmatrix.sync.aligned.m8n8.x4.trans.shared.b16 {%0,%1,%2,%3}, [%4];"
                 : "=r"(r0), "=r"(r1), "=r"(r2), "=r"(r3) : "r"(addr));
}

__device__ __forceinline__ void cp16(uint32_t saddr, const void* gaddr) {
    asm volatile("cp.async.cg.shared.global [%0], [%1], 16;"
                 :: "r"(saddr), "l"(gaddr) : "memory");
}
#define CP_COMMIT() asm volatile("cp.async.commit_group;" ::: "memory")
#define CP_WAIT0()  asm volatile("cp.async.wait_group 0;"  ::: "memory")

// ---------------- fp32 -> fp16 converts ----------------
// hi + lo split (for X)
__global__ __launch_bounds__(256) void convert_hl_kernel(
    const float* __restrict__ src, fp16* __restrict__ h, fp16* __restrict__ l, int n4)
{
    const int i = blockIdx.x * blockDim.x + threadIdx.x;
    if (i >= n4) return;
    float4 v = reinterpret_cast<const float4*>(src)[i];
    uint32_t h0, l0, h1, l1;
    split2h(v.x, v.y, h0, l0);
    split2h(v.z, v.w, h1, l1);
    reinterpret_cast<uint32_t*>(h)[i * 2]     = h0;
    reinterpret_cast<uint32_t*>(h)[i * 2 + 1] = h1;
    reinterpret_cast<uint32_t*>(l)[i * 2]     = l0;
    reinterpret_cast<uint32_t*>(l)[i * 2 + 1] = l1;
}

// hi only (for Wo)
__global__ __launch_bounds__(256) void convert_h_kernel(
    const float* __restrict__ src, fp16* __restrict__ h, int n4)
{
    const int i = blockIdx.x * blockDim.x + threadIdx.x;
    if (i >= n4) return;
    float4 v = reinterpret_cast<const float4*>(src)[i];
    reinterpret_cast<uint32_t*>(h)[i * 2]     = pack2h(v.x, v.y);
    reinterpret_cast<uint32_t*>(h)[i * 2 + 1] = pack2h(v.z, v.w);
}

// W [2048, Nsrc] fp32 -> combined [2048, NC] fp16 hi at column offset
__global__ __launch_bounds__(256) void convW_kernel(
    const float* __restrict__ src, fp16* __restrict__ h, int Nsrc, int colOff, int n4)
{
    const int i = blockIdx.x * blockDim.x + threadIdx.x;
    if (i >= n4) return;
    const int perRow = Nsrc >> 2;
    const int k = i / perRow;
    const int c4 = (i - k * perRow) * 4;
    float4 v = reinterpret_cast<const float4*>(src)[i];
    const size_t o = ((size_t)k * NC + colOff + c4) >> 1;  // uint32 index
    reinterpret_cast<uint32_t*>(h)[o]     = pack2h(v.x, v.y);
    reinterpret_cast<uint32_t*>(h)[o + 1] = pack2h(v.z, v.w);
}

// ---------------------------------------------------------------------------
// 2-term fp16 GEMM: C = (Ah+Al) @ Bh + bias. CTA 128x128, BK=32, 256 threads
// (8 warps 4x2, warp tile 32x64), cp.async double buffer + ldmatrix.
// MODE 0: fp32 +bias -> Cf (O projection)
// MODE 4: combined QKV epilogue: Q -> hi/lo [b,h,s,d]; K -> hi [b,g,s,d]
//         scaled by 0.125*log2e; V -> hi transposed [b,g,d,s]
// ---------------------------------------------------------------------------
#define GAP 40     // A smem pitch (fp16): 32 k + 8 pad
#define GBP 136    // B smem pitch (fp16): 128 n + 8 pad
#define GA_BYTES (128 * GAP * 2)            // 10240
#define GB_BYTES (32 * GBP * 2)             // 8704
#define GSTAGE   (2 * GA_BYTES + GB_BYTES)  // 29184
#define GEMM_SMEM (2 * GSTAGE)              // 58368
#define KSCALE (0.125f * 1.44269504088896f)

template<int MODE>
__global__ __launch_bounds__(256, 2) void gemm_kernel(
    const fp16* __restrict__ Ah, const fp16* __restrict__ Al,
    const fp16* __restrict__ Bh,
    const float* __restrict__ bias0, const float* __restrict__ bias1,
    const float* __restrict__ bias2,
    float* __restrict__ Cf, int M, int N, int K)
{
    extern __shared__ char smc[];
    const uint32_t sbase = (uint32_t)__cvta_generic_to_shared(smc);

    const int tid  = threadIdx.x;
    const int lane = tid & 31;
    const int wid  = tid >> 5;
    const int g = lane >> 2, c = lane & 3;
    const int quad = lane >> 3, r8 = lane & 7;
    const int wm0 = (wid & 3) * 32;
    const int wn0 = (wid >> 2) * 64;
    const int row0 = blockIdx.y * 128;
    const int col0 = blockIdx.x * 128;

    float acc[2][8][4];
    #pragma unroll
    for (int mt = 0; mt < 2; mt++)
        #pragma unroll
        for (int nt = 0; nt < 8; nt++)
            #pragma unroll
            for (int j = 0; j < 4; j++) acc[mt][nt][j] = 0.0f;

    const int NT = K / 32;

    auto fill = [&](int kt, int st) {
        const int k0 = kt * 32;
        const uint32_t s0 = sbase + st * GSTAGE;
        #pragma unroll
        for (int i = 0; i < 2; i++) {
            const int idx = tid + i * 256;
            const int r = idx >> 2, q = (idx & 3) * 8;
            const size_t go = (size_t)(row0 + r) * K + k0 + q;
            cp16(s0 + (r * GAP + q) * 2,            Ah + go);
            cp16(s0 + GA_BYTES + (r * GAP + q) * 2, Al + go);
        }
        #pragma unroll
        for (int i = 0; i < 2; i++) {
            const int idx = tid + i * 256;
            const int r = idx >> 4, q = (idx & 15) * 8;
            const size_t go = (size_t)(k0 + r) * N + col0 + q;
            cp16(s0 + 2 * GA_BYTES + (r * GBP + q) * 2, Bh + go);
        }
    };

    fill(0, 0); CP_COMMIT();

    const int arow = (quad & 1) * 8 + r8;
    const int acol = (quad >> 1) * 8;

    for (int kt = 0; kt < NT; kt++) {
        CP_WAIT0();
        __syncthreads();
        if (kt + 1 < NT) { fill(kt + 1, (kt + 1) & 1); CP_COMMIT(); }
        const uint32_t s0 = sbase + (kt & 1) * GSTAGE;

        #pragma unroll
        for (int kk = 0; kk < 2; kk++) {
            uint32_t ah[2][4], al[2][4];
            #pragma unroll
            for (int mt = 0; mt < 2; mt++) {
                const uint32_t aaddr =
                    s0 + ((wm0 + mt * 16 + arow) * GAP + kk * 16 + acol) * 2;
                ldsm4(ah[mt][0], ah[mt][1], ah[mt][2], ah[mt][3], aaddr);
                ldsm4(al[mt][0], al[mt][1], al[mt][2], al[mt][3], aaddr + GA_BYTES);
            }
            #pragma unroll
            for (int np = 0; np < 4; np++) {
                const uint32_t baddr = s0 + 2 * GA_BYTES +
                    ((kk * 16 + arow) * GBP + wn0 + np * 16 + acol) * 2;
                uint32_t bh0, bh1, bh2, bh3;
                ldsm4t(bh0, bh1, bh2, bh3, baddr);
                #pragma unroll
                for (int mt = 0; mt < 2; mt++) {
                    mma_f16(acc[mt][2*np],   al[mt], bh0, bh1);
                    mma_f16(acc[mt][2*np],   ah[mt], bh0, bh1);
                    mma_f16(acc[mt][2*np+1], al[mt], bh2, bh3);
                    mma_f16(acc[mt][2*np+1], ah[mt], bh2, bh3);
                }
            }
        }
    }

    // ---- epilogue ----
    #pragma unroll
    for (int mt = 0; mt < 2; mt++) {
        const int r = row0 + wm0 + mt * 16 + g;     // and r+8
        const int b0 = r >> 11, s0i = r & 2047;
        const int b1 = (r + 8) >> 11, s1i = (r + 8) & 2047;
        #pragma unroll
        for (int nt = 0; nt < 8; nt++) {
            const int n = col0 + wn0 + nt * 8 + 2 * c;
            if (MODE == 0) {
                const float bv0 = bias0[n], bv1 = bias0[n + 1];
                const float v0 = acc[mt][nt][0] + bv0;
                const float v1 = acc[mt][nt][1] + bv1;
                const float v2 = acc[mt][nt][2] + bv0;
                const float v3 = acc[mt][nt][3] + bv1;
                *(float2*)(Cf + (size_t)r * N + n)       = make_float2(v0, v1);
                *(float2*)(Cf + (size_t)(r + 8) * N + n) = make_float2(v2, v3);
            } else {
                if (n < HID) {               // ---- Q: hi/lo [b,h,s,d] ----
                    const float bv0 = bias0[n], bv1 = bias0[n + 1];
                    const float v0 = acc[mt][nt][0] + bv0;
                    const float v1 = acc[mt][nt][1] + bv1;
                    const float v2 = acc[mt][nt][2] + bv0;
                    const float v3 = acc[mt][nt][3] + bv1;
                    const int hh = n >> 6, d = n & 63;
                    uint32_t ph, pl;
                    split2h(v0, v1, ph, pl);
                    size_t o0 = (((size_t)(b0 * NH + hh)) * SEQ + s0i) * HD + d;
                    *reinterpret_cast<uint32_t*>(g_qh + o0) = ph;
                    *reinterpret_cast<uint32_t*>(g_ql + o0) = pl;
                    split2h(v2, v3, ph, pl);
                    size_t o1 = (((size_t)(b1 * NH + hh)) * SEQ + s1i) * HD + d;
                    *reinterpret_cast<uint32_t*>(g_qh + o1) = ph;
                    *reinterpret_cast<uint32_t*>(g_ql + o1) = pl;
                } else if (n < HID + KVD) {  // ---- K: hi [b,g,s,d], xKSCALE ----
                    const int nn = n - HID;
                    const float bv0 = bias1[nn], bv1 = bias1[nn + 1];
                    const float v0 = (acc[mt][nt][0] + bv0) * KSCALE;
                    const float v1 = (acc[mt][nt][1] + bv1) * KSCALE;
                    const float v2 = (acc[mt][nt][2] + bv0) * KSCALE;
                    const float v3 = (acc[mt][nt][3] + bv1) * KSCALE;
                    const int gg = nn >> 6, d = nn & 63;
                    size_t o0 = (((size_t)(b0 * NG + gg)) * SEQ + s0i) * HD + d;
                    size_t o1 = (((size_t)(b1 * NG + gg)) * SEQ + s1i) * HD + d;
                    *reinterpret_cast<uint32_t*>(g_kh + o0) = pack2h(v0, v1);
                    *reinterpret_cast<uint32_t*>(g_kh + o1) = pack2h(v2, v3);
                } else {                     // ---- V: hi transposed [b,g,d,s] ----
                    const int nn = n - HID - KVD;
                    const float bv0 = bias2[nn], bv1 = bias2[nn + 1];
                    const float vals[4] = {
                        acc[mt][nt][0] + bv0, acc[mt][nt][1] + bv1,
                        acc[mt][nt][2] + bv0, acc[mt][nt][3] + bv1 };
                    const int gg = nn >> 6, d = nn & 63;
                    const size_t base0 = ((size_t)(b0 * NG + gg)) * HD;
                    const size_t base1 = ((size_t)(b1 * NG + gg)) * HD;
                    const size_t offs[4] = {
                        (base0 + d) * SEQ + s0i, (base0 + d + 1) * SEQ + s0i,
                        (base1 + d) * SEQ + s1i, (base1 + d + 1) * SEQ + s1i };
                    #pragma unroll
                    for (int j = 0; j < 4; j++)
                        g_vh[offs[j]] = __float2half_rn(vals[j]);
                }
            }
        }
    }
}

// ---------------------------------------------------------------------------
// Flash attention, 2-term fp16. Q hi/lo in registers, K/V hi-only in smem
// (half the fill traffic of R7), P split hi/lo in registers, exp2 softmax.
// Block = (b, h, 128-query tile), 256 threads.
// smem/stage: Kh [64 key][72 d] + Vh [64 d][72 key] fp16 = 18432 B.
// ---------------------------------------------------------------------------
#define AKP 72
#define AK_BYTES (64 * AKP * 2)        // 9216
#define ASTAGE   (2 * AK_BYTES)        // 18432
#define ATTN_SMEM (2 * ASTAGE)         // 36864

__global__ __launch_bounds__(256, 2) void attn_kernel(
    const fp16* __restrict__ Qh, const fp16* __restrict__ Ql,
    const fp16* __restrict__ Kh, const fp16* __restrict__ Vh,
    fp16* __restrict__ Oh, fp16* __restrict__ Ol)
{
    extern __shared__ char smc[];
    const uint32_t sbase = (uint32_t)__cvta_generic_to_shared(smc);

    const int tid  = threadIdx.x;
    const int lane = tid & 31;
    const int wid  = tid >> 5;
    const int g = lane >> 2, c = lane & 3;
    const int quad = lane >> 3, r8 = lane & 7;
    const int wr0 = wid * 16;
    const int lrow = (quad >> 1) * 8 + r8;
    const int lcol = (quad & 1) * 8;

    const int qt = blockIdx.x;
    const int h  = blockIdx.y;
    const int b  = blockIdx.z;
    const int gh = h >> 2;

    const size_t koff = ((size_t)(b * NG + gh)) * SEQ * HD;
    const size_t voff = ((size_t)(b * NG + gh)) * HD * SEQ;

    const fp16* qbh = Qh + (((size_t)(b * NH + h)) * SEQ + qt * 128 + wr0) * HD;
    const fp16* qbl = Ql + (((size_t)(b * NH + h)) * SEQ + qt * 128 + wr0) * HD;
    uint32_t qh[4][4], ql[4][4];
    #pragma unroll
    for (int kt = 0; kt < 4; kt++) {
        const int o0 = g * HD + kt * 16 + 2 * c;
        qh[kt][0] = *(const uint32_t*)(qbh + o0);
        qh[kt][1] = *(const uint32_t*)(qbh + o0 + 8 * HD);
        qh[kt][2] = *(const uint32_t*)(qbh + o0 + 8);
        qh[kt][3] = *(const uint32_t*)(qbh + o0 + 8 * HD + 8);
        ql[kt][0] = *(const uint32_t*)(qbl + o0);
        ql[kt][1] = *(const uint32_t*)(qbl + o0 + 8 * HD);
        ql[kt][2] = *(const uint32_t*)(qbl + o0 + 8);
        ql[kt][3] = *(const uint32_t*)(qbl + o0 + 8 * HD + 8);
    }

    auto fill = [&](int t, int st) {
        const uint32_t s0 = sbase + st * ASTAGE;
        #pragma unroll
        for (int i = 0; i < 2; i++) {
            const int idx = tid + i * 256;
            const int r = idx >> 3, q = (idx & 7) * 8;
            const uint32_t so = (r * AKP + q) * 2;
            const size_t gk = koff + (size_t)(t * 64 + r) * HD + q;
            cp16(s0 + so, Kh + gk);
            const size_t gv = voff + (size_t)r * SEQ + t * 64 + q;
            cp16(s0 + AK_BYTES + so, Vh + gv);
        }
    };

    float m0 = -1e30f, m1 = -1e30f, l0 = 0.0f, l1 = 0.0f;
    float oacc[8][4];
    #pragma unroll
    for (int nt = 0; nt < 8; nt++)
        #pragma unroll
        for (int j = 0; j < 4; j++) oacc[nt][j] = 0.0f;

    fill(0, 0); CP_COMMIT();

    for (int t = 0; t < SEQ / 64; t++) {
        CP_WAIT0();
        __syncthreads();
        if (t + 1 < SEQ / 64) { fill(t + 1, (t + 1) & 1); CP_COMMIT(); }
        const uint32_t sK = sbase + (t & 1) * ASTAGE;
        const uint32_t sV = sK + AK_BYTES;

        // ---- S = Q @ K^T (2-term fp16) ----
        float sv[8][4];
        #pragma unroll
        for (int nt = 0; nt < 8; nt++)
            #pragma unroll
            for (int j = 0; j < 4; j++) sv[nt][j] = 0.0f;

        #pragma unroll
        for (int np = 0; np < 4; np++) {
            #pragma unroll
            for (int kt = 0; kt < 4; kt++) {
                const uint32_t ka = sK + ((np * 16 + lrow) * AKP + kt * 16 + lcol) * 2;
                uint32_t h0, h1, h2, h3;
                ldsm4(h0, h1, h2, h3, ka);
                mma_f16(sv[2*np],   ql[kt], h0, h1);
                mma_f16(sv[2*np],   qh[kt], h0, h1);
                mma_f16(sv[2*np+1], ql[kt], h2, h3);
                mma_f16(sv[2*np+1], qh[kt], h2, h3);
            }
        }

        // ---- online softmax (exp2; log2e folded into K) ----
        float mx0 = -1e30f, mx1 = -1e30f;
        #pragma unroll
        for (int nt = 0; nt < 8; nt++) {
            mx0 = fmaxf(mx0, fmaxf(sv[nt][0], sv[nt][1]));
            mx1 = fmaxf(mx1, fmaxf(sv[nt][2], sv[nt][3]));
        }
        mx0 = fmaxf(mx0, __shfl_xor_sync(0xffffffffu, mx0, 1));
        mx0 = fmaxf(mx0, __shfl_xor_sync(0xffffffffu, mx0, 2));
        mx1 = fmaxf(mx1, __shfl_xor_sync(0xffffffffu, mx1, 1));
        mx1 = fmaxf(mx1, __shfl_xor_sync(0xffffffffu, mx1, 2));

        const float nm0 = fmaxf(m0, mx0), nm1 = fmaxf(m1, mx1);
        const float corr0 = exp2f(m0 - nm0), corr1 = exp2f(m1 - nm1);
        float ls0 = 0.0f, ls1 = 0.0f;
        #pragma unroll
        for (int nt = 0; nt < 8; nt++) {
            sv[nt][0] = exp2f(sv[nt][0] - nm0);
            sv[nt][1] = exp2f(sv[nt][1] - nm0);
            sv[nt][2] = exp2f(sv[nt][2] - nm1);
            sv[nt][3] = exp2f(sv[nt][3] - nm1);
            ls0 += sv[nt][0] + sv[nt][1];
            ls1 += sv[nt][2] + sv[nt][3];
        }
        ls0 += __shfl_xor_sync(0xffffffffu, ls0, 1);
        ls0 += __shfl_xor_sync(0xffffffffu, ls0, 2);
        ls1 += __shfl_xor_sync(0xffffffffu, ls1, 1);
        ls1 += __shfl_xor_sync(0xffffffffu, ls1, 2);
        l0 = l0 * corr0 + ls0; m0 = nm0;
        l1 = l1 * corr1 + ls1; m1 = nm1;
        #pragma unroll
        for (int nt = 0; nt < 8; nt++) {
            oacc[nt][0] *= corr0; oacc[nt][1] *= corr0;
            oacc[nt][2] *= corr1; oacc[nt][3] *= corr1;
        }

        // ---- O += P @ V (P hi/lo in registers, V hi in smem) ----
        #pragma unroll
        for (int kt = 0; kt < 4; kt++) {
            uint32_t ph[4], pl[4];
            split2h(sv[2*kt][0],   sv[2*kt][1],   ph[0], pl[0]);
            split2h(sv[2*kt][2],   sv[2*kt][3],   ph[1], pl[1]);
            split2h(sv[2*kt+1][0], sv[2*kt+1][1], ph[2], pl[2]);
            split2h(sv[2*kt+1][2], sv[2*kt+1][3], ph[3], pl[3]);
            #pragma unroll
            for (int np = 0; np < 4; np++) {
                const uint32_t va = sV + ((np * 16 + lrow) * AKP + kt * 16 + lcol) * 2;
                uint32_t h0, h1, h2, h3;
                ldsm4(h0, h1, h2, h3, va);
                mma_f16(oacc[2*np],   pl, h0, h1);
                mma_f16(oacc[2*np],   ph, h0, h1);
                mma_f16(oacc[2*np+1], pl, h2, h3);
                mma_f16(oacc[2*np+1], ph, h2, h3);
            }
        }
    }

    // ---- epilogue: normalize, split, store fp16 hi/lo to [b,s,h*64+d] ----
    const float inv0 = 1.0f / l0, inv1 = 1.0f / l1;
    const int s0 = qt * 128 + wr0 + g;
    const size_t ob0 = ((size_t)b * SEQ + s0) * HID + h * HD;
    const size_t ob1 = ((size_t)b * SEQ + s0 + 8) * HID + h * HD;
    #pragma unroll
    for (int nt = 0; nt < 8; nt++) {
        const int d = nt * 8 + 2 * c;
        uint32_t ph, pl;
        split2h(oacc[nt][0] * inv0, oacc[nt][1] * inv0, ph, pl);
        *reinterpret_cast<uint32_t*>(Oh + ob0 + d) = ph;
        *reinterpret_cast<uint32_t*>(Ol + ob0 + d) = pl;
        split2h(oacc[nt][2] * inv1, oacc[nt][3] * inv1, ph, pl);
        *reinterpret_cast<uint32_t*>(Oh + ob1 + d) = ph;
        *reinterpret_cast<uint32_t*>(Ol + ob1 + d) = pl;
    }
}

// ---------------------------------------------------------------------------
extern "C" void kernel_launch(void* const* d_in, const int* in_sizes, int n_in,
                              void* d_out, int out_size)
{
    const float* X  = (const float*)d_in[0];
    const float* Wq = (const float*)d_in[1];
    const float* bq = (const float*)d_in[2];
    const float* Wk = (const float*)d_in[3];
    const float* bk = (const float*)d_in[4];
    const float* Wv = (const float*)d_in[5];
    const float* bv = (const float*)d_in[6];
    const float* Wo = (const float*)d_in[7];
    const float* bo = (const float*)d_in[8];
    float* out = (float*)d_out;

    fp16 *xh, *xl, *wch, *woh, *qh, *ql, *kh, *vh, *oh, *ol;
    cudaGetSymbolAddress((void**)&xh,  g_xh);  cudaGetSymbolAddress((void**)&xl,  g_xl);
    cudaGetSymbolAddress((void**)&wch, g_wch); cudaGetSymbolAddress((void**)&woh, g_woh);
    cudaGetSymbolAddress((void**)&qh,  g_qh);  cudaGetSymbolAddress((void**)&ql,  g_ql);
    cudaGetSymbolAddress((void**)&kh,  g_kh);  cudaGetSymbolAddress((void**)&vh,  g_vh);
    cudaGetSymbolAddress((void**)&oh,  g_oh);  cudaGetSymbolAddress((void**)&ol,  g_ol);

    cudaFuncSetAttribute(gemm_kernel<0>, cudaFuncAttributeMaxDynamicSharedMemorySize, GEMM_SMEM);
    cudaFuncSetAttribute(gemm_kernel<4>, cudaFuncAttributeMaxDynamicSharedMemorySize, GEMM_SMEM);
    cudaFuncSetAttribute(attn_kernel, cudaFuncAttributeMaxDynamicSharedMemorySize, ATTN_SMEM);

    // ---- converts ----
    {
        const int n4 = MTOT * HID / 4;
        convert_hl_kernel<<<(n4 + 255) / 256, 256>>>(X, xh, xl, n4);
    }
    {   // Wq/Wk/Wv -> combined [2048, 3072] hi only
        int n4q = HID * HID / 4;
        convW_kernel<<<(n4q + 255) / 256, 256>>>(Wq, wch, HID, 0, n4q);
        int n4k = HID * KVD / 4;
        convW_kernel<<<(n4k + 255) / 256, 256>>>(Wk, wch, KVD, HID, n4k);
        convW_kernel<<<(n4k + 255) / 256, 256>>>(Wv, wch, KVD, HID + KVD, n4k);
    }
    {
        const int n4 = HID * HID / 4;
        convert_h_kernel<<<(n4 + 255) / 256, 256>>>(Wo, woh, n4);
    }

    dim3 blk(256);
    // Fused QKV projection: [4096,2048] @ [2048,3072]
    gemm_kernel<4><<<dim3(NC / 128, MTOT / 128), blk, GEMM_SMEM>>>(
        xh, xl, wch, bq, bk, bv, nullptr, MTOT, NC, HID);
    // Attention -> fp16 hi/lo [b,s,h*d]
    attn_kernel<<<dim3(SEQ / 128, NH, BATCH), blk, ATTN_SMEM>>>(
        qh, ql, kh, vh, oh, ol);
    // Output projection -> fp32 d_out
    gemm_kernel<0><<<dim3(HID / 128, MTOT / 128), blk, GEMM_SMEM>>>(
        oh, ol, woh, bo, nullptr, nullptr, out, MTOT, HID, HID);
}

// round 10
// speedup vs baseline: 1.5986x; 1.0935x over previous
#include <cuda_runtime.h>
#include <cuda_fp16.h>
#include <cstdint>

#define BATCH 2
#define SEQ   2048
#define HID   2048
#define NH    32
#define NG    8
#define HD    64
#define KVD   (NG*HD)     // 512
#define MTOT  (BATCH*SEQ) // 4096
#define NC    (HID + 2*KVD)  // 3072 combined QKV cols

typedef __half fp16;

// ---------------- device scratch (no allocation allowed) ----------------
__device__ fp16 g_xh[(size_t)MTOT*HID],  g_xl[(size_t)MTOT*HID];
__device__ fp16 g_wch[(size_t)HID*NC];                            // [K, Q|K|V] hi only
__device__ fp16 g_woh[(size_t)HID*HID];                           // [K,N] hi only
__device__ fp16 g_qh[(size_t)BATCH*NH*SEQ*HD], g_ql[(size_t)BATCH*NH*SEQ*HD];
__device__ fp16 g_kh[(size_t)BATCH*NG*SEQ*HD];                    // hi only
__device__ fp16 g_vh[(size_t)BATCH*NG*HD*SEQ];                    // [b,g,d,s] hi only
__device__ fp16 g_oh[(size_t)MTOT*HID],  g_ol[(size_t)MTOT*HID];

// ---------------- helpers ----------------
__device__ __forceinline__ void split2h(float x0, float x1, uint32_t& h, uint32_t& l) {
    __half2 hb = __floats2half2_rn(x0, x1);
    const float r0 = x0 - __half2float(__low2half(hb));
    const float r1 = x1 - __half2float(__high2half(hb));
    __half2 lb = __floats2half2_rn(r0, r1);
    h = *reinterpret_cast<uint32_t*>(&hb);
    l = *reinterpret_cast<uint32_t*>(&lb);
}
__device__ __forceinline__ uint32_t pack2h(float x0, float x1) {
    __half2 hb = __floats2half2_rn(x0, x1);
    return *reinterpret_cast<uint32_t*>(&hb);
}

__device__ __forceinline__ void mma_f16(float d[4], const uint32_t a[4],
                                        uint32_t b0, uint32_t b1) {
    asm volatile(
        "mma.sync.aligned.m16n8k16.row.col.f32.f16.f16.f32 "
        "{%0,%1,%2,%3}, {%4,%5,%6,%7}, {%8,%9}, {%0,%1,%2,%3};\n"
        : "+f"(d[0]), "+f"(d[1]), "+f"(d[2]), "+f"(d[3])
        : "r"(a[0]), "r"(a[1]), "r"(a[2]), "r"(a[3]), "r"(b0), "r"(b1));
}

__device__ __forceinline__ void ldsm4(uint32_t& r0, uint32_t& r1, uint32_t& r2,
                                      uint32_t& r3, uint32_t addr) {
    asm volatile("ldmatrix.sync.aligned.m8n8.x4.shared.b16 {%0,%1,%2,%3}, [%4];"
                 : "=r"(r0), "=r"(r1), "=r"(r2), "=r"(r3) : "r"(addr));
}
__device__ __forceinline__ void ldsm4t(uint32_t& r0, uint32_t& r1, uint32_t& r2,
                                       uint32_t& r3, uint32_t addr) {
    asm volatile("ldmatrix.sync.aligned.m8n8.x4.trans.shared.b16 {%0,%1,%2,%3}, [%4];"
                 : "=r"(r0), "=r"(r1), "=r"(r2), "=r"(r3) : "r"(addr));
}

__device__ __forceinline__ void cp16(uint32_t saddr, const void* gaddr) {
    asm volatile("cp.async.cg.shared.global [%0], [%1], 16;"
                 :: "r"(saddr), "l"(gaddr) : "memory");
}
#define CP_COMMIT() asm volatile("cp.async.commit_group;" ::: "memory")
#define CP_WAIT0()  asm volatile("cp.async.wait_group 0;"  ::: "memory")

// ---------------- fp32 -> fp16 converts ----------------
__global__ __launch_bounds__(256) void convert_hl_kernel(
    const float* __restrict__ src, fp16* __restrict__ h, fp16* __restrict__ l, int n4)
{
    const int i = blockIdx.x * blockDim.x + threadIdx.x;
    if (i >= n4) return;
    float4 v = reinterpret_cast<const float4*>(src)[i];
    uint32_t h0, l0, h1, l1;
    split2h(v.x, v.y, h0, l0);
    split2h(v.z, v.w, h1, l1);
    reinterpret_cast<uint32_t*>(h)[i * 2]     = h0;
    reinterpret_cast<uint32_t*>(h)[i * 2 + 1] = h1;
    reinterpret_cast<uint32_t*>(l)[i * 2]     = l0;
    reinterpret_cast<uint32_t*>(l)[i * 2 + 1] = l1;
}

__global__ __launch_bounds__(256) void convert_h_kernel(
    const float* __restrict__ src, fp16* __restrict__ h, int n4)
{
    const int i = blockIdx.x * blockDim.x + threadIdx.x;
    if (i >= n4) return;
    float4 v = reinterpret_cast<const float4*>(src)[i];
    reinterpret_cast<uint32_t*>(h)[i * 2]     = pack2h(v.x, v.y);
    reinterpret_cast<uint32_t*>(h)[i * 2 + 1] = pack2h(v.z, v.w);
}

// W [2048, Nsrc] fp32 -> combined [2048, NC] fp16 hi at column offset
__global__ __launch_bounds__(256) void convW_kernel(
    const float* __restrict__ src, fp16* __restrict__ h, int Nsrc, int colOff, int n4)
{
    const int i = blockIdx.x * blockDim.x + threadIdx.x;
    if (i >= n4) return;
    const int perRow = Nsrc >> 2;
    const int k = i / perRow;
    const int c4 = (i - k * perRow) * 4;
    float4 v = reinterpret_cast<const float4*>(src)[i];
    const size_t o = ((size_t)k * NC + colOff + c4) >> 1;  // uint32 index
    reinterpret_cast<uint32_t*>(h)[o]     = pack2h(v.x, v.y);
    reinterpret_cast<uint32_t*>(h)[o + 1] = pack2h(v.z, v.w);
}

// ---------------------------------------------------------------------------
// 2-term fp16 GEMM: C = (Ah+Al) @ Bh + bias. CTA 128x128, BK=32, 256 threads
// (8 warps 4x2, warp tile 32x64), cp.async double buffer + ldmatrix.
// MODE 0: fp32 +bias -> Cf (O projection)
// MODE 4: combined QKV epilogue: Q -> hi/lo [b,h,s,d]; K -> hi [b,g,s,d]
//         scaled by 0.125*log2e; V -> hi transposed [b,g,d,s]
// ---------------------------------------------------------------------------
#define GAP 40     // A smem pitch (fp16): 32 k + 8 pad
#define GBP 136    // B smem pitch (fp16): 128 n + 8 pad
#define GA_BYTES (128 * GAP * 2)            // 10240
#define GB_BYTES (32 * GBP * 2)             // 8704
#define GSTAGE   (2 * GA_BYTES + GB_BYTES)  // 29184
#define GEMM_SMEM (2 * GSTAGE)              // 58368
#define KSCALE (0.125f * 1.44269504088896f)

template<int MODE>
__global__ __launch_bounds__(256, 2) void gemm_kernel(
    const fp16* __restrict__ Ah, const fp16* __restrict__ Al,
    const fp16* __restrict__ Bh,
    const float* __restrict__ bias0, const float* __restrict__ bias1,
    const float* __restrict__ bias2,
    float* __restrict__ Cf, int M, int N, int K)
{
    extern __shared__ char smc[];
    const uint32_t sbase = (uint32_t)__cvta_generic_to_shared(smc);

    const int tid  = threadIdx.x;
    const int lane = tid & 31;
    const int wid  = tid >> 5;
    const int g = lane >> 2, c = lane & 3;
    const int quad = lane >> 3, r8 = lane & 7;
    const int wm0 = (wid & 3) * 32;
    const int wn0 = (wid >> 2) * 64;
    const int row0 = blockIdx.y * 128;
    const int col0 = blockIdx.x * 128;

    float acc[2][8][4];
    #pragma unroll
    for (int mt = 0; mt < 2; mt++)
        #pragma unroll
        for (int nt = 0; nt < 8; nt++)
            #pragma unroll
            for (int j = 0; j < 4; j++) acc[mt][nt][j] = 0.0f;

    const int NT = K / 32;

    auto fill = [&](int kt, int st) {
        const int k0 = kt * 32;
        const uint32_t s0 = sbase + st * GSTAGE;
        #pragma unroll
        for (int i = 0; i < 2; i++) {
            const int idx = tid + i * 256;
            const int r = idx >> 2, q = (idx & 3) * 8;
            const size_t go = (size_t)(row0 + r) * K + k0 + q;
            cp16(s0 + (r * GAP + q) * 2,            Ah + go);
            cp16(s0 + GA_BYTES + (r * GAP + q) * 2, Al + go);
        }
        #pragma unroll
        for (int i = 0; i < 2; i++) {
            const int idx = tid + i * 256;
            const int r = idx >> 4, q = (idx & 15) * 8;
            const size_t go = (size_t)(k0 + r) * N + col0 + q;
            cp16(s0 + 2 * GA_BYTES + (r * GBP + q) * 2, Bh + go);
        }
    };

    fill(0, 0); CP_COMMIT();

    const int arow = (quad & 1) * 8 + r8;
    const int acol = (quad >> 1) * 8;

    for (int kt = 0; kt < NT; kt++) {
        CP_WAIT0();
        __syncthreads();
        if (kt + 1 < NT) { fill(kt + 1, (kt + 1) & 1); CP_COMMIT(); }
        const uint32_t s0 = sbase + (kt & 1) * GSTAGE;

        #pragma unroll
        for (int kk = 0; kk < 2; kk++) {
            uint32_t ah[2][4], al[2][4];
            #pragma unroll
            for (int mt = 0; mt < 2; mt++) {
                const uint32_t aaddr =
                    s0 + ((wm0 + mt * 16 + arow) * GAP + kk * 16 + acol) * 2;
                ldsm4(ah[mt][0], ah[mt][1], ah[mt][2], ah[mt][3], aaddr);
                ldsm4(al[mt][0], al[mt][1], al[mt][2], al[mt][3], aaddr + GA_BYTES);
            }
            #pragma unroll
            for (int np = 0; np < 4; np++) {
                const uint32_t baddr = s0 + 2 * GA_BYTES +
                    ((kk * 16 + arow) * GBP + wn0 + np * 16 + acol) * 2;
                uint32_t bh0, bh1, bh2, bh3;
                ldsm4t(bh0, bh1, bh2, bh3, baddr);
                #pragma unroll
                for (int mt = 0; mt < 2; mt++) {
                    mma_f16(acc[mt][2*np],   al[mt], bh0, bh1);
                    mma_f16(acc[mt][2*np],   ah[mt], bh0, bh1);
                    mma_f16(acc[mt][2*np+1], al[mt], bh2, bh3);
                    mma_f16(acc[mt][2*np+1], ah[mt], bh2, bh3);
                }
            }
        }
    }

    // ---- epilogue ----
    #pragma unroll
    for (int mt = 0; mt < 2; mt++) {
        const int r = row0 + wm0 + mt * 16 + g;     // and r+8
        const int b0 = r >> 11, s0i = r & 2047;
        const int b1 = (r + 8) >> 11, s1i = (r + 8) & 2047;
        #pragma unroll
        for (int nt = 0; nt < 8; nt++) {
            const int n = col0 + wn0 + nt * 8 + 2 * c;
            if (MODE == 0) {
                const float bv0 = bias0[n], bv1 = bias0[n + 1];
                const float v0 = acc[mt][nt][0] + bv0;
                const float v1 = acc[mt][nt][1] + bv1;
                const float v2 = acc[mt][nt][2] + bv0;
                const float v3 = acc[mt][nt][3] + bv1;
                *(float2*)(Cf + (size_t)r * N + n)       = make_float2(v0, v1);
                *(float2*)(Cf + (size_t)(r + 8) * N + n) = make_float2(v2, v3);
            } else {
                if (n < HID) {               // ---- Q: hi/lo [b,h,s,d] ----
                    const float bv0 = bias0[n], bv1 = bias0[n + 1];
                    const float v0 = acc[mt][nt][0] + bv0;
                    const float v1 = acc[mt][nt][1] + bv1;
                    const float v2 = acc[mt][nt][2] + bv0;
                    const float v3 = acc[mt][nt][3] + bv1;
                    const int hh = n >> 6, d = n & 63;
                    uint32_t ph, pl;
                    split2h(v0, v1, ph, pl);
                    size_t o0 = (((size_t)(b0 * NH + hh)) * SEQ + s0i) * HD + d;
                    *reinterpret_cast<uint32_t*>(g_qh + o0) = ph;
                    *reinterpret_cast<uint32_t*>(g_ql + o0) = pl;
                    split2h(v2, v3, ph, pl);
                    size_t o1 = (((size_t)(b1 * NH + hh)) * SEQ + s1i) * HD + d;
                    *reinterpret_cast<uint32_t*>(g_qh + o1) = ph;
                    *reinterpret_cast<uint32_t*>(g_ql + o1) = pl;
                } else if (n < HID + KVD) {  // ---- K: hi [b,g,s,d], xKSCALE ----
                    const int nn = n - HID;
                    const float bv0 = bias1[nn], bv1 = bias1[nn + 1];
                    const float v0 = (acc[mt][nt][0] + bv0) * KSCALE;
                    const float v1 = (acc[mt][nt][1] + bv1) * KSCALE;
                    const float v2 = (acc[mt][nt][2] + bv0) * KSCALE;
                    const float v3 = (acc[mt][nt][3] + bv1) * KSCALE;
                    const int gg = nn >> 6, d = nn & 63;
                    size_t o0 = (((size_t)(b0 * NG + gg)) * SEQ + s0i) * HD + d;
                    size_t o1 = (((size_t)(b1 * NG + gg)) * SEQ + s1i) * HD + d;
                    *reinterpret_cast<uint32_t*>(g_kh + o0) = pack2h(v0, v1);
                    *reinterpret_cast<uint32_t*>(g_kh + o1) = pack2h(v2, v3);
                } else {                     // ---- V: hi transposed [b,g,d,s] ----
                    const int nn = n - HID - KVD;
                    const float bv0 = bias2[nn], bv1 = bias2[nn + 1];
                    const float vals[4] = {
                        acc[mt][nt][0] + bv0, acc[mt][nt][1] + bv1,
                        acc[mt][nt][2] + bv0, acc[mt][nt][3] + bv1 };
                    const int gg = nn >> 6, d = nn & 63;
                    const size_t base0 = ((size_t)(b0 * NG + gg)) * HD;
                    const size_t base1 = ((size_t)(b1 * NG + gg)) * HD;
                    const size_t offs[4] = {
                        (base0 + d) * SEQ + s0i, (base0 + d + 1) * SEQ + s0i,
                        (base1 + d) * SEQ + s1i, (base1 + d + 1) * SEQ + s1i };
                    #pragma unroll
                    for (int j = 0; j < 4; j++)
                        g_vh[offs[j]] = __float2half_rn(vals[j]);
                }
            }
        }
    }
}

// ---------------------------------------------------------------------------
// Flash attention. Q hi/lo (2-term QK), P packed fp16 1-term PV (P in [0,1];
// its fp16 rounding error ~2^-11 is at the existing error floor), K/V hi-only
// in smem, exp2 softmax. Block = (b, h, 128-query tile), 256 threads.
// ---------------------------------------------------------------------------
#define AKP 72
#define AK_BYTES (64 * AKP * 2)        // 9216
#define ASTAGE   (2 * AK_BYTES)        // 18432
#define ATTN_SMEM (2 * ASTAGE)         // 36864

__global__ __launch_bounds__(256, 2) void attn_kernel(
    const fp16* __restrict__ Qh, const fp16* __restrict__ Ql,
    const fp16* __restrict__ Kh, const fp16* __restrict__ Vh,
    fp16* __restrict__ Oh, fp16* __restrict__ Ol)
{
    extern __shared__ char smc[];
    const uint32_t sbase = (uint32_t)__cvta_generic_to_shared(smc);

    const int tid  = threadIdx.x;
    const int lane = tid & 31;
    const int wid  = tid >> 5;
    const int g = lane >> 2, c = lane & 3;
    const int quad = lane >> 3, r8 = lane & 7;
    const int wr0 = wid * 16;
    const int lrow = (quad >> 1) * 8 + r8;
    const int lcol = (quad & 1) * 8;

    const int qt = blockIdx.x;
    const int h  = blockIdx.y;
    const int b  = blockIdx.z;
    const int gh = h >> 2;

    const size_t koff = ((size_t)(b * NG + gh)) * SEQ * HD;
    const size_t voff = ((size_t)(b * NG + gh)) * HD * SEQ;

    const fp16* qbh = Qh + (((size_t)(b * NH + h)) * SEQ + qt * 128 + wr0) * HD;
    const fp16* qbl = Ql + (((size_t)(b * NH + h)) * SEQ + qt * 128 + wr0) * HD;
    uint32_t qh[4][4], ql[4][4];
    #pragma unroll
    for (int kt = 0; kt < 4; kt++) {
        const int o0 = g * HD + kt * 16 + 2 * c;
        qh[kt][0] = *(const uint32_t*)(qbh + o0);
        qh[kt][1] = *(const uint32_t*)(qbh + o0 + 8 * HD);
        qh[kt][2] = *(const uint32_t*)(qbh + o0 + 8);
        qh[kt][3] = *(const uint32_t*)(qbh + o0 + 8 * HD + 8);
        ql[kt][0] = *(const uint32_t*)(qbl + o0);
        ql[kt][1] = *(const uint32_t*)(qbl + o0 + 8 * HD);
        ql[kt][2] = *(const uint32_t*)(qbl + o0 + 8);
        ql[kt][3] = *(const uint32_t*)(qbl + o0 + 8 * HD + 8);
    }

    auto fill = [&](int t, int st) {
        const uint32_t s0 = sbase + st * ASTAGE;
        #pragma unroll
        for (int i = 0; i < 2; i++) {
            const int idx = tid + i * 256;
            const int r = idx >> 3, q = (idx & 7) * 8;
            const uint32_t so = (r * AKP + q) * 2;
            const size_t gk = koff + (size_t)(t * 64 + r) * HD + q;
            cp16(s0 + so, Kh + gk);
            const size_t gv = voff + (size_t)r * SEQ + t * 64 + q;
            cp16(s0 + AK_BYTES + so, Vh + gv);
        }
    };

    float m0 = -1e30f, m1 = -1e30f, l0 = 0.0f, l1 = 0.0f;
    float oacc[8][4];
    #pragma unroll
    for (int nt = 0; nt < 8; nt++)
        #pragma unroll
        for (int j = 0; j < 4; j++) oacc[nt][j] = 0.0f;

    fill(0, 0); CP_COMMIT();

    for (int t = 0; t < SEQ / 64; t++) {
        CP_WAIT0();
        __syncthreads();
        if (t + 1 < SEQ / 64) { fill(t + 1, (t + 1) & 1); CP_COMMIT(); }
        const uint32_t sK = sbase + (t & 1) * ASTAGE;
        const uint32_t sV = sK + AK_BYTES;

        // ---- S = Q @ K^T (2-term fp16) ----
        float sv[8][4];
        #pragma unroll
        for (int nt = 0; nt < 8; nt++)
            #pragma unroll
            for (int j = 0; j < 4; j++) sv[nt][j] = 0.0f;

        #pragma unroll
        for (int np = 0; np < 4; np++) {
            #pragma unroll
            for (int kt = 0; kt < 4; kt++) {
                const uint32_t ka = sK + ((np * 16 + lrow) * AKP + kt * 16 + lcol) * 2;
                uint32_t h0, h1, h2, h3;
                ldsm4(h0, h1, h2, h3, ka);
                mma_f16(sv[2*np],   ql[kt], h0, h1);
                mma_f16(sv[2*np],   qh[kt], h0, h1);
                mma_f16(sv[2*np+1], ql[kt], h2, h3);
                mma_f16(sv[2*np+1], qh[kt], h2, h3);
            }
        }

        // ---- online softmax (exp2; log2e folded into K) ----
        float mx0 = -1e30f, mx1 = -1e30f;
        #pragma unroll
        for (int nt = 0; nt < 8; nt++) {
            mx0 = fmaxf(mx0, fmaxf(sv[nt][0], sv[nt][1]));
            mx1 = fmaxf(mx1, fmaxf(sv[nt][2], sv[nt][3]));
        }
        mx0 = fmaxf(mx0, __shfl_xor_sync(0xffffffffu, mx0, 1));
        mx0 = fmaxf(mx0, __shfl_xor_sync(0xffffffffu, mx0, 2));
        mx1 = fmaxf(mx1, __shfl_xor_sync(0xffffffffu, mx1, 1));
        mx1 = fmaxf(mx1, __shfl_xor_sync(0xffffffffu, mx1, 2));

        const float nm0 = fmaxf(m0, mx0), nm1 = fmaxf(m1, mx1);
        const float corr0 = exp2f(m0 - nm0), corr1 = exp2f(m1 - nm1);
        float ls0 = 0.0f, ls1 = 0.0f;
        #pragma unroll
        for (int nt = 0; nt < 8; nt++) {
            sv[nt][0] = exp2f(sv[nt][0] - nm0);
            sv[nt][1] = exp2f(sv[nt][1] - nm0);
            sv[nt][2] = exp2f(sv[nt][2] - nm1);
            sv[nt][3] = exp2f(sv[nt][3] - nm1);
            ls0 += sv[nt][0] + sv[nt][1];
            ls1 += sv[nt][2] + sv[nt][3];
        }
        ls0 += __shfl_xor_sync(0xffffffffu, ls0, 1);
        ls0 += __shfl_xor_sync(0xffffffffu, ls0, 2);
        ls1 += __shfl_xor_sync(0xffffffffu, ls1, 1);
        ls1 += __shfl_xor_sync(0xffffffffu, ls1, 2);
        l0 = l0 * corr0 + ls0; m0 = nm0;
        l1 = l1 * corr1 + ls1; m1 = nm1;
        #pragma unroll
        for (int nt = 0; nt < 8; nt++) {
            oacc[nt][0] *= corr0; oacc[nt][1] *= corr0;
            oacc[nt][2] *= corr1; oacc[nt][3] *= corr1;
        }

        // ---- O += P @ V (P packed fp16, 1-term; V hi in smem) ----
        #pragma unroll
        for (int kt = 0; kt < 4; kt++) {
            uint32_t ph[4];
            ph[0] = pack2h(sv[2*kt][0],   sv[2*kt][1]);
            ph[1] = pack2h(sv[2*kt][2],   sv[2*kt][3]);
            ph[2] = pack2h(sv[2*kt+1][0], sv[2*kt+1][1]);
            ph[3] = pack2h(sv[2*kt+1][2], sv[2*kt+1][3]);
            #pragma unroll
            for (int np = 0; np < 4; np++) {
                const uint32_t va = sV + ((np * 16 + lrow) * AKP + kt * 16 + lcol) * 2;
                uint32_t h0, h1, h2, h3;
                ldsm4(h0, h1, h2, h3, va);
                mma_f16(oacc[2*np],   ph, h0, h1);
                mma_f16(oacc[2*np+1], ph, h2, h3);
            }
        }
    }

    // ---- epilogue: normalize, split, store fp16 hi/lo to [b,s,h*64+d] ----
    const float inv0 = 1.0f / l0, inv1 = 1.0f / l1;
    const int s0 = qt * 128 + wr0 + g;
    const size_t ob0 = ((size_t)b * SEQ + s0) * HID + h * HD;
    const size_t ob1 = ((size_t)b * SEQ + s0 + 8) * HID + h * HD;
    #pragma unroll
    for (int nt = 0; nt < 8; nt++) {
        const int d = nt * 8 + 2 * c;
        uint32_t ph, pl;
        split2h(oacc[nt][0] * inv0, oacc[nt][1] * inv0, ph, pl);
        *reinterpret_cast<uint32_t*>(Oh + ob0 + d) = ph;
        *reinterpret_cast<uint32_t*>(Ol + ob0 + d) = pl;
        split2h(oacc[nt][2] * inv1, oacc[nt][3] * inv1, ph, pl);
        *reinterpret_cast<uint32_t*>(Oh + ob1 + d) = ph;
        *reinterpret_cast<uint32_t*>(Ol + ob1 + d) = pl;
    }
}

// ---------------------------------------------------------------------------
extern "C" void kernel_launch(void* const* d_in, const int* in_sizes, int n_in,
                              void* d_out, int out_size)
{
    const float* X  = (const float*)d_in[0];
    const float* Wq = (const float*)d_in[1];
    const float* bq = (const float*)d_in[2];
    const float* Wk = (const float*)d_in[3];
    const float* bk = (const float*)d_in[4];
    const float* Wv = (const float*)d_in[5];
    const float* bv = (const float*)d_in[6];
    const float* Wo = (const float*)d_in[7];
    const float* bo = (const float*)d_in[8];
    float* out = (float*)d_out;

    fp16 *xh, *xl, *wch, *woh, *qh, *ql, *kh, *vh, *oh, *ol;
    cudaGetSymbolAddress((void**)&xh,  g_xh);  cudaGetSymbolAddress((void**)&xl,  g_xl);
    cudaGetSymbolAddress((void**)&wch, g_wch); cudaGetSymbolAddress((void**)&woh, g_woh);
    cudaGetSymbolAddress((void**)&qh,  g_qh);  cudaGetSymbolAddress((void**)&ql,  g_ql);
    cudaGetSymbolAddress((void**)&kh,  g_kh);  cudaGetSymbolAddress((void**)&vh,  g_vh);
    cudaGetSymbolAddress((void**)&oh,  g_oh);  cudaGetSymbolAddress((void**)&ol,  g_ol);

    cudaFuncSetAttribute(gemm_kernel<0>, cudaFuncAttributeMaxDynamicSharedMemorySize, GEMM_SMEM);
    cudaFuncSetAttribute(gemm_kernel<4>, cudaFuncAttributeMaxDynamicSharedMemorySize, GEMM_SMEM);
    cudaFuncSetAttribute(attn_kernel, cudaFuncAttributeMaxDynamicSharedMemorySize, ATTN_SMEM);

    // ---- converts ----
    {
        const int n4 = MTOT * HID / 4;
        convert_hl_kernel<<<(n4 + 255) / 256, 256>>>(X, xh, xl, n4);
    }
    {   // Wq/Wk/Wv -> combined [2048, 3072] hi only
        int n4q = HID * HID / 4;
        convW_kernel<<<(n4q + 255) / 256, 256>>>(Wq, wch, HID, 0, n4q);
        int n4k = HID * KVD / 4;
        convW_kernel<<<(n4k + 255) / 256, 256>>>(Wk, wch, KVD, HID, n4k);
        convW_kernel<<<(n4k + 255) / 256, 256>>>(Wv, wch, KVD, HID + KVD, n4k);
    }
    {
        const int n4 = HID * HID / 4;
        convert_h_kernel<<<(n4 + 255) / 256, 256>>>(Wo, woh, n4);
    }

    dim3 blk(256);
    // Fused QKV projection: [4096,2048] @ [2048,3072]
    gemm_kernel<4><<<dim3(NC / 128, MTOT / 128), blk, GEMM_SMEM>>>(
        xh, xl, wch, bq, bk, bv, nullptr, MTOT, NC, HID);
    // Attention -> fp16 hi/lo [b,s,h*d]
    attn_kernel<<<dim3(SEQ / 128, NH, BATCH), blk, ATTN_SMEM>>>(
        qh, ql, kh, vh, oh, ol);
    // Output projection -> fp32 d_out
    gemm_kernel<0><<<dim3(HID / 128, MTOT / 128), blk, GEMM_SMEM>>>(
        oh, ol, woh, bo, nullptr, nullptr, out, MTOT, HID, HID);
}

// round 11
// speedup vs baseline: 1.9821x; 1.2399x over previous
#include <cuda_runtime.h>
#include <cuda_fp16.h>
#include <cstdint>

#define BATCH 2
#define SEQ   2048
#define HID   2048
#define NH    32
#define NG    8
#define HD    64
#define KVD   (NG*HD)     // 512
#define MTOT  (BATCH*SEQ) // 4096
#define NC    (HID + 2*KVD)  // 3072 combined QKV cols

typedef __half fp16;

// ---------------- device scratch (no allocation allowed) ----------------
__device__ fp16 g_xh[(size_t)MTOT*HID],  g_xl[(size_t)MTOT*HID];
__device__ fp16 g_wch[(size_t)HID*NC];                            // [K, Q|K|V] hi only
__device__ fp16 g_woh[(size_t)HID*HID];                           // [K,N] hi only
__device__ fp16 g_qh[(size_t)BATCH*NH*SEQ*HD];                    // hi only
__device__ fp16 g_kh[(size_t)BATCH*NG*SEQ*HD];                    // hi only
__device__ fp16 g_vh[(size_t)BATCH*NG*HD*SEQ];                    // [b,g,d,s] hi only
__device__ fp16 g_oh[(size_t)MTOT*HID];                           // hi only

// ---------------- helpers ----------------
__device__ __forceinline__ void split2h(float x0, float x1, uint32_t& h, uint32_t& l) {
    __half2 hb = __floats2half2_rn(x0, x1);
    const float r0 = x0 - __half2float(__low2half(hb));
    const float r1 = x1 - __half2float(__high2half(hb));
    __half2 lb = __floats2half2_rn(r0, r1);
    h = *reinterpret_cast<uint32_t*>(&hb);
    l = *reinterpret_cast<uint32_t*>(&lb);
}
__device__ __forceinline__ uint32_t pack2h(float x0, float x1) {
    __half2 hb = __floats2half2_rn(x0, x1);
    return *reinterpret_cast<uint32_t*>(&hb);
}

__device__ __forceinline__ void mma_f16(float d[4], const uint32_t a[4],
                                        uint32_t b0, uint32_t b1) {
    asm volatile(
        "mma.sync.aligned.m16n8k16.row.col.f32.f16.f16.f32 "
        "{%0,%1,%2,%3}, {%4,%5,%6,%7}, {%8,%9}, {%0,%1,%2,%3};\n"
        : "+f"(d[0]), "+f"(d[1]), "+f"(d[2]), "+f"(d[3])
        : "r"(a[0]), "r"(a[1]), "r"(a[2]), "r"(a[3]), "r"(b0), "r"(b1));
}

__device__ __forceinline__ void ldsm4(uint32_t& r0, uint32_t& r1, uint32_t& r2,
                                      uint32_t& r3, uint32_t addr) {
    asm volatile("ldmatrix.sync.aligned.m8n8.x4.shared.b16 {%0,%1,%2,%3}, [%4];"
                 : "=r"(r0), "=r"(r1), "=r"(r2), "=r"(r3) : "r"(addr));
}
__device__ __forceinline__ void ldsm4t(uint32_t& r0, uint32_t& r1, uint32_t& r2,
                                       uint32_t& r3, uint32_t addr) {
    asm volatile("ldmatrix.sync.aligned.m8n8.x4.trans.shared.b16 {%0,%1,%2,%3}, [%4];"
                 : "=r"(r0), "=r"(r1), "=r"(r2), "=r"(r3) : "r"(addr));
}

__device__ __forceinline__ void cp16(uint32_t saddr, const void* gaddr) {
    asm volatile("cp.async.cg.shared.global [%0], [%1], 16;"
                 :: "r"(saddr), "l"(gaddr) : "memory");
}
#define CP_COMMIT() asm volatile("cp.async.commit_group;" ::: "memory")
#define CP_WAIT0()  asm volatile("cp.async.wait_group 0;"  ::: "memory")

// ---------------- fp32 -> fp16 converts ----------------
__global__ __launch_bounds__(256) void convert_hl_kernel(
    const float* __restrict__ src, fp16* __restrict__ h, fp16* __restrict__ l, int n4)
{
    const int i = blockIdx.x * blockDim.x + threadIdx.x;
    if (i >= n4) return;
    float4 v = reinterpret_cast<const float4*>(src)[i];
    uint32_t h0, l0, h1, l1;
    split2h(v.x, v.y, h0, l0);
    split2h(v.z, v.w, h1, l1);
    reinterpret_cast<uint32_t*>(h)[i * 2]     = h0;
    reinterpret_cast<uint32_t*>(h)[i * 2 + 1] = h1;
    reinterpret_cast<uint32_t*>(l)[i * 2]     = l0;
    reinterpret_cast<uint32_t*>(l)[i * 2 + 1] = l1;
}

__global__ __launch_bounds__(256) void convert_h_kernel(
    const float* __restrict__ src, fp16* __restrict__ h, int n4)
{
    const int i = blockIdx.x * blockDim.x + threadIdx.x;
    if (i >= n4) return;
    float4 v = reinterpret_cast<const float4*>(src)[i];
    reinterpret_cast<uint32_t*>(h)[i * 2]     = pack2h(v.x, v.y);
    reinterpret_cast<uint32_t*>(h)[i * 2 + 1] = pack2h(v.z, v.w);
}

// W [2048, Nsrc] fp32 -> combined [2048, NC] fp16 hi at column offset
__global__ __launch_bounds__(256) void convW_kernel(
    const float* __restrict__ src, fp16* __restrict__ h, int Nsrc, int colOff, int n4)
{
    const int i = blockIdx.x * blockDim.x + threadIdx.x;
    if (i >= n4) return;
    const int perRow = Nsrc >> 2;
    const int k = i / perRow;
    const int c4 = (i - k * perRow) * 4;
    float4 v = reinterpret_cast<const float4*>(src)[i];
    const size_t o = ((size_t)k * NC + colOff + c4) >> 1;  // uint32 index
    reinterpret_cast<uint32_t*>(h)[o]     = pack2h(v.x, v.y);
    reinterpret_cast<uint32_t*>(h)[o + 1] = pack2h(v.z, v.w);
}

// ---------------------------------------------------------------------------
// fp16 GEMM: C = (Ah[+Al]) @ Bh + bias. CTA 128x128, BK=32, 256 threads
// (8 warps 4x2, warp tile 32x64), cp.async double buffer + ldmatrix.
// TERMS=2: A split hi/lo (2 MMAs per frag); TERMS=1: A hi-only.
// MODE 0: fp32 +bias -> Cf (O projection)
// MODE 4: combined QKV epilogue: Q -> hi [b,h,s,d]; K -> hi [b,g,s,d]
//         scaled by 0.125*log2e; V -> hi transposed [b,g,d,s]
// ---------------------------------------------------------------------------
#define GAP 40     // A smem pitch (fp16): 32 k + 8 pad
#define GBP 136    // B smem pitch (fp16): 128 n + 8 pad
#define GA_BYTES (128 * GAP * 2)            // 10240
#define GB_BYTES (32 * GBP * 2)             // 8704
#define GSTAGE   (2 * GA_BYTES + GB_BYTES)  // 29184 (lo region unused if TERMS=1)
#define GEMM_SMEM (2 * GSTAGE)              // 58368
#define KSCALE (0.125f * 1.44269504088896f)

template<int MODE, int TERMS>
__global__ __launch_bounds__(256, 2) void gemm_kernel(
    const fp16* __restrict__ Ah, const fp16* __restrict__ Al,
    const fp16* __restrict__ Bh,
    const float* __restrict__ bias0, const float* __restrict__ bias1,
    const float* __restrict__ bias2,
    float* __restrict__ Cf, int M, int N, int K)
{
    extern __shared__ char smc[];
    const uint32_t sbase = (uint32_t)__cvta_generic_to_shared(smc);

    const int tid  = threadIdx.x;
    const int lane = tid & 31;
    const int wid  = tid >> 5;
    const int g = lane >> 2, c = lane & 3;
    const int quad = lane >> 3, r8 = lane & 7;
    const int wm0 = (wid & 3) * 32;
    const int wn0 = (wid >> 2) * 64;
    const int row0 = blockIdx.y * 128;
    const int col0 = blockIdx.x * 128;

    float acc[2][8][4];
    #pragma unroll
    for (int mt = 0; mt < 2; mt++)
        #pragma unroll
        for (int nt = 0; nt < 8; nt++)
            #pragma unroll
            for (int j = 0; j < 4; j++) acc[mt][nt][j] = 0.0f;

    const int NT = K / 32;

    auto fill = [&](int kt, int st) {
        const int k0 = kt * 32;
        const uint32_t s0 = sbase + st * GSTAGE;
        #pragma unroll
        for (int i = 0; i < 2; i++) {
            const int idx = tid + i * 256;
            const int r = idx >> 2, q = (idx & 3) * 8;
            const size_t go = (size_t)(row0 + r) * K + k0 + q;
            cp16(s0 + (r * GAP + q) * 2, Ah + go);
            if (TERMS == 2)
                cp16(s0 + GA_BYTES + (r * GAP + q) * 2, Al + go);
        }
        #pragma unroll
        for (int i = 0; i < 2; i++) {
            const int idx = tid + i * 256;
            const int r = idx >> 4, q = (idx & 15) * 8;
            const size_t go = (size_t)(k0 + r) * N + col0 + q;
            cp16(s0 + 2 * GA_BYTES + (r * GBP + q) * 2, Bh + go);
        }
    };

    fill(0, 0); CP_COMMIT();

    const int arow = (quad & 1) * 8 + r8;
    const int acol = (quad >> 1) * 8;

    for (int kt = 0; kt < NT; kt++) {
        CP_WAIT0();
        __syncthreads();
        if (kt + 1 < NT) { fill(kt + 1, (kt + 1) & 1); CP_COMMIT(); }
        const uint32_t s0 = sbase + (kt & 1) * GSTAGE;

        #pragma unroll
        for (int kk = 0; kk < 2; kk++) {
            uint32_t ah[2][4], al[2][4];
            #pragma unroll
            for (int mt = 0; mt < 2; mt++) {
                const uint32_t aaddr =
                    s0 + ((wm0 + mt * 16 + arow) * GAP + kk * 16 + acol) * 2;
                ldsm4(ah[mt][0], ah[mt][1], ah[mt][2], ah[mt][3], aaddr);
                if (TERMS == 2)
                    ldsm4(al[mt][0], al[mt][1], al[mt][2], al[mt][3], aaddr + GA_BYTES);
            }
            #pragma unroll
            for (int np = 0; np < 4; np++) {
                const uint32_t baddr = s0 + 2 * GA_BYTES +
                    ((kk * 16 + arow) * GBP + wn0 + np * 16 + acol) * 2;
                uint32_t bh0, bh1, bh2, bh3;
                ldsm4t(bh0, bh1, bh2, bh3, baddr);
                #pragma unroll
                for (int mt = 0; mt < 2; mt++) {
                    if (TERMS == 2) {
                        mma_f16(acc[mt][2*np],   al[mt], bh0, bh1);
                        mma_f16(acc[mt][2*np+1], al[mt], bh2, bh3);
                    }
                    mma_f16(acc[mt][2*np],   ah[mt], bh0, bh1);
                    mma_f16(acc[mt][2*np+1], ah[mt], bh2, bh3);
                }
            }
        }
    }

    // ---- epilogue ----
    #pragma unroll
    for (int mt = 0; mt < 2; mt++) {
        const int r = row0 + wm0 + mt * 16 + g;     // and r+8
        const int b0 = r >> 11, s0i = r & 2047;
        const int b1 = (r + 8) >> 11, s1i = (r + 8) & 2047;
        #pragma unroll
        for (int nt = 0; nt < 8; nt++) {
            const int n = col0 + wn0 + nt * 8 + 2 * c;
            if (MODE == 0) {
                const float bv0 = bias0[n], bv1 = bias0[n + 1];
                const float v0 = acc[mt][nt][0] + bv0;
                const float v1 = acc[mt][nt][1] + bv1;
                const float v2 = acc[mt][nt][2] + bv0;
                const float v3 = acc[mt][nt][3] + bv1;
                *(float2*)(Cf + (size_t)r * N + n)       = make_float2(v0, v1);
                *(float2*)(Cf + (size_t)(r + 8) * N + n) = make_float2(v2, v3);
            } else {
                if (n < HID) {               // ---- Q: hi [b,h,s,d] ----
                    const float bv0 = bias0[n], bv1 = bias0[n + 1];
                    const int hh = n >> 6, d = n & 63;
                    size_t o0 = (((size_t)(b0 * NH + hh)) * SEQ + s0i) * HD + d;
                    size_t o1 = (((size_t)(b1 * NH + hh)) * SEQ + s1i) * HD + d;
                    *reinterpret_cast<uint32_t*>(g_qh + o0) =
                        pack2h(acc[mt][nt][0] + bv0, acc[mt][nt][1] + bv1);
                    *reinterpret_cast<uint32_t*>(g_qh + o1) =
                        pack2h(acc[mt][nt][2] + bv0, acc[mt][nt][3] + bv1);
                } else if (n < HID + KVD) {  // ---- K: hi [b,g,s,d], xKSCALE ----
                    const int nn = n - HID;
                    const float bv0 = bias1[nn], bv1 = bias1[nn + 1];
                    const float v0 = (acc[mt][nt][0] + bv0) * KSCALE;
                    const float v1 = (acc[mt][nt][1] + bv1) * KSCALE;
                    const float v2 = (acc[mt][nt][2] + bv0) * KSCALE;
                    const float v3 = (acc[mt][nt][3] + bv1) * KSCALE;
                    const int gg = nn >> 6, d = nn & 63;
                    size_t o0 = (((size_t)(b0 * NG + gg)) * SEQ + s0i) * HD + d;
                    size_t o1 = (((size_t)(b1 * NG + gg)) * SEQ + s1i) * HD + d;
                    *reinterpret_cast<uint32_t*>(g_kh + o0) = pack2h(v0, v1);
                    *reinterpret_cast<uint32_t*>(g_kh + o1) = pack2h(v2, v3);
                } else {                     // ---- V: hi transposed [b,g,d,s] ----
                    const int nn = n - HID - KVD;
                    const float bv0 = bias2[nn], bv1 = bias2[nn + 1];
                    const float vals[4] = {
                        acc[mt][nt][0] + bv0, acc[mt][nt][1] + bv1,
                        acc[mt][nt][2] + bv0, acc[mt][nt][3] + bv1 };
                    const int gg = nn >> 6, d = nn & 63;
                    const size_t base0 = ((size_t)(b0 * NG + gg)) * HD;
                    const size_t base1 = ((size_t)(b1 * NG + gg)) * HD;
                    const size_t offs[4] = {
                        (base0 + d) * SEQ + s0i, (base0 + d + 1) * SEQ + s0i,
                        (base1 + d) * SEQ + s1i, (base1 + d + 1) * SEQ + s1i };
                    #pragma unroll
                    for (int j = 0; j < 4; j++)
                        g_vh[offs[j]] = __float2half_rn(vals[j]);
                }
            }
        }
    }
}

// ---------------------------------------------------------------------------
// Flash attention: 1-term fp16 QK (Q hi-only) + 1-term PV (P fp16), K/V
// hi-only in smem, exp2 softmax. Incoherent-rounding analysis: each hi-only
// operand adds ~2.5-3e-4 rel err in quadrature (reduction dims 64/2048).
// Block = (b, h, 128-query tile), 256 threads.
// ---------------------------------------------------------------------------
#define AKP 72
#define AK_BYTES (64 * AKP * 2)        // 9216
#define ASTAGE   (2 * AK_BYTES)        // 18432
#define ATTN_SMEM (2 * ASTAGE)         // 36864

__global__ __launch_bounds__(256, 2) void attn_kernel(
    const fp16* __restrict__ Qh, const fp16* __restrict__ Kh,
    const fp16* __restrict__ Vh, fp16* __restrict__ Oh)
{
    extern __shared__ char smc[];
    const uint32_t sbase = (uint32_t)__cvta_generic_to_shared(smc);

    const int tid  = threadIdx.x;
    const int lane = tid & 31;
    const int wid  = tid >> 5;
    const int g = lane >> 2, c = lane & 3;
    const int quad = lane >> 3, r8 = lane & 7;
    const int wr0 = wid * 16;
    const int lrow = (quad >> 1) * 8 + r8;
    const int lcol = (quad & 1) * 8;

    const int qt = blockIdx.x;
    const int h  = blockIdx.y;
    const int b  = blockIdx.z;
    const int gh = h >> 2;

    const size_t koff = ((size_t)(b * NG + gh)) * SEQ * HD;
    const size_t voff = ((size_t)(b * NG + gh)) * HD * SEQ;

    const fp16* qbh = Qh + (((size_t)(b * NH + h)) * SEQ + qt * 128 + wr0) * HD;
    uint32_t qh[4][4];
    #pragma unroll
    for (int kt = 0; kt < 4; kt++) {
        const int o0 = g * HD + kt * 16 + 2 * c;
        qh[kt][0] = *(const uint32_t*)(qbh + o0);
        qh[kt][1] = *(const uint32_t*)(qbh + o0 + 8 * HD);
        qh[kt][2] = *(const uint32_t*)(qbh + o0 + 8);
        qh[kt][3] = *(const uint32_t*)(qbh + o0 + 8 * HD + 8);
    }

    auto fill = [&](int t, int st) {
        const uint32_t s0 = sbase + st * ASTAGE;
        #pragma unroll
        for (int i = 0; i < 2; i++) {
            const int idx = tid + i * 256;
            const int r = idx >> 3, q = (idx & 7) * 8;
            const uint32_t so = (r * AKP + q) * 2;
            const size_t gk = koff + (size_t)(t * 64 + r) * HD + q;
            cp16(s0 + so, Kh + gk);
            const size_t gv = voff + (size_t)r * SEQ + t * 64 + q;
            cp16(s0 + AK_BYTES + so, Vh + gv);
        }
    };

    float m0 = -1e30f, m1 = -1e30f, l0 = 0.0f, l1 = 0.0f;
    float oacc[8][4];
    #pragma unroll
    for (int nt = 0; nt < 8; nt++)
        #pragma unroll
        for (int j = 0; j < 4; j++) oacc[nt][j] = 0.0f;

    fill(0, 0); CP_COMMIT();

    for (int t = 0; t < SEQ / 64; t++) {
        CP_WAIT0();
        __syncthreads();
        if (t + 1 < SEQ / 64) { fill(t + 1, (t + 1) & 1); CP_COMMIT(); }
        const uint32_t sK = sbase + (t & 1) * ASTAGE;
        const uint32_t sV = sK + AK_BYTES;

        // ---- S = Q @ K^T (1-term fp16) ----
        float sv[8][4];
        #pragma unroll
        for (int nt = 0; nt < 8; nt++)
            #pragma unroll
            for (int j = 0; j < 4; j++) sv[nt][j] = 0.0f;

        #pragma unroll
        for (int np = 0; np < 4; np++) {
            #pragma unroll
            for (int kt = 0; kt < 4; kt++) {
                const uint32_t ka = sK + ((np * 16 + lrow) * AKP + kt * 16 + lcol) * 2;
                uint32_t h0, h1, h2, h3;
                ldsm4(h0, h1, h2, h3, ka);
                mma_f16(sv[2*np],   qh[kt], h0, h1);
                mma_f16(sv[2*np+1], qh[kt], h2, h3);
            }
        }

        // ---- online softmax (exp2; log2e folded into K) ----
        float mx0 = -1e30f, mx1 = -1e30f;
        #pragma unroll
        for (int nt = 0; nt < 8; nt++) {
            mx0 = fmaxf(mx0, fmaxf(sv[nt][0], sv[nt][1]));
            mx1 = fmaxf(mx1, fmaxf(sv[nt][2], sv[nt][3]));
        }
        mx0 = fmaxf(mx0, __shfl_xor_sync(0xffffffffu, mx0, 1));
        mx0 = fmaxf(mx0, __shfl_xor_sync(0xffffffffu, mx0, 2));
        mx1 = fmaxf(mx1, __shfl_xor_sync(0xffffffffu, mx1, 1));
        mx1 = fmaxf(mx1, __shfl_xor_sync(0xffffffffu, mx1, 2));

        const float nm0 = fmaxf(m0, mx0), nm1 = fmaxf(m1, mx1);
        const float corr0 = exp2f(m0 - nm0), corr1 = exp2f(m1 - nm1);
        float ls0 = 0.0f, ls1 = 0.0f;
        #pragma unroll
        for (int nt = 0; nt < 8; nt++) {
            sv[nt][0] = exp2f(sv[nt][0] - nm0);
            sv[nt][1] = exp2f(sv[nt][1] - nm0);
            sv[nt][2] = exp2f(sv[nt][2] - nm1);
            sv[nt][3] = exp2f(sv[nt][3] - nm1);
            ls0 += sv[nt][0] + sv[nt][1];
            ls1 += sv[nt][2] + sv[nt][3];
        }
        ls0 += __shfl_xor_sync(0xffffffffu, ls0, 1);
        ls0 += __shfl_xor_sync(0xffffffffu, ls0, 2);
        ls1 += __shfl_xor_sync(0xffffffffu, ls1, 1);
        ls1 += __shfl_xor_sync(0xffffffffu, ls1, 2);
        l0 = l0 * corr0 + ls0; m0 = nm0;
        l1 = l1 * corr1 + ls1; m1 = nm1;
        #pragma unroll
        for (int nt = 0; nt < 8; nt++) {
            oacc[nt][0] *= corr0; oacc[nt][1] *= corr0;
            oacc[nt][2] *= corr1; oacc[nt][3] *= corr1;
        }

        // ---- O += P @ V (P packed fp16, 1-term; V hi in smem) ----
        #pragma unroll
        for (int kt = 0; kt < 4; kt++) {
            uint32_t ph[4];
            ph[0] = pack2h(sv[2*kt][0],   sv[2*kt][1]);
            ph[1] = pack2h(sv[2*kt][2],   sv[2*kt][3]);
            ph[2] = pack2h(sv[2*kt+1][0], sv[2*kt+1][1]);
            ph[3] = pack2h(sv[2*kt+1][2], sv[2*kt+1][3]);
            #pragma unroll
            for (int np = 0; np < 4; np++) {
                const uint32_t va = sV + ((np * 16 + lrow) * AKP + kt * 16 + lcol) * 2;
                uint32_t h0, h1, h2, h3;
                ldsm4(h0, h1, h2, h3, va);
                mma_f16(oacc[2*np],   ph, h0, h1);
                mma_f16(oacc[2*np+1], ph, h2, h3);
            }
        }
    }

    // ---- epilogue: normalize, store fp16 hi to [b,s,h*64+d] ----
    const float inv0 = 1.0f / l0, inv1 = 1.0f / l1;
    const int s0 = qt * 128 + wr0 + g;
    const size_t ob0 = ((size_t)b * SEQ + s0) * HID + h * HD;
    const size_t ob1 = ((size_t)b * SEQ + s0 + 8) * HID + h * HD;
    #pragma unroll
    for (int nt = 0; nt < 8; nt++) {
        const int d = nt * 8 + 2 * c;
        *reinterpret_cast<uint32_t*>(Oh + ob0 + d) =
            pack2h(oacc[nt][0] * inv0, oacc[nt][1] * inv0);
        *reinterpret_cast<uint32_t*>(Oh + ob1 + d) =
            pack2h(oacc[nt][2] * inv1, oacc[nt][3] * inv1);
    }
}

// ---------------------------------------------------------------------------
extern "C" void kernel_launch(void* const* d_in, const int* in_sizes, int n_in,
                              void* d_out, int out_size)
{
    const float* X  = (const float*)d_in[0];
    const float* Wq = (const float*)d_in[1];
    const float* bq = (const float*)d_in[2];
    const float* Wk = (const float*)d_in[3];
    const float* bk = (const float*)d_in[4];
    const float* Wv = (const float*)d_in[5];
    const float* bv = (const float*)d_in[6];
    const float* Wo = (const float*)d_in[7];
    const float* bo = (const float*)d_in[8];
    float* out = (float*)d_out;

    fp16 *xh, *xl, *wch, *woh, *qh, *kh, *vh, *oh;
    cudaGetSymbolAddress((void**)&xh,  g_xh);  cudaGetSymbolAddress((void**)&xl,  g_xl);
    cudaGetSymbolAddress((void**)&wch, g_wch); cudaGetSymbolAddress((void**)&woh, g_woh);
    cudaGetSymbolAddress((void**)&qh,  g_qh);
    cudaGetSymbolAddress((void**)&kh,  g_kh);  cudaGetSymbolAddress((void**)&vh,  g_vh);
    cudaGetSymbolAddress((void**)&oh,  g_oh);

    cudaFuncSetAttribute((const void*)gemm_kernel<0,1>,
                         cudaFuncAttributeMaxDynamicSharedMemorySize, GEMM_SMEM);
    cudaFuncSetAttribute((const void*)gemm_kernel<4,2>,
                         cudaFuncAttributeMaxDynamicSharedMemorySize, GEMM_SMEM);
    cudaFuncSetAttribute(attn_kernel, cudaFuncAttributeMaxDynamicSharedMemorySize, ATTN_SMEM);

    // ---- converts ----
    {
        const int n4 = MTOT * HID / 4;
        convert_hl_kernel<<<(n4 + 255) / 256, 256>>>(X, xh, xl, n4);
    }
    {   // Wq/Wk/Wv -> combined [2048, 3072] hi only
        int n4q = HID * HID / 4;
        convW_kernel<<<(n4q + 255) / 256, 256>>>(Wq, wch, HID, 0, n4q);
        int n4k = HID * KVD / 4;
        convW_kernel<<<(n4k + 255) / 256, 256>>>(Wk, wch, KVD, HID, n4k);
        convW_kernel<<<(n4k + 255) / 256, 256>>>(Wv, wch, KVD, HID + KVD, n4k);
    }
    {
        const int n4 = HID * HID / 4;
        convert_h_kernel<<<(n4 + 255) / 256, 256>>>(Wo, woh, n4);
    }

    dim3 blk(256);
    // Fused QKV projection (2-term: X hi/lo): [4096,2048] @ [2048,3072]
    gemm_kernel<4,2><<<dim3(NC / 128, MTOT / 128), blk, GEMM_SMEM>>>(
        xh, xl, wch, bq, bk, bv, nullptr, MTOT, NC, HID);
    // Attention -> fp16 hi [b,s,h*d]
    attn_kernel<<<dim3(SEQ / 128, NH, BATCH), blk, ATTN_SMEM>>>(
        qh, kh, vh, oh);
    // Output projection (1-term) -> fp32 d_out
    gemm_kernel<0,1><<<dim3(HID / 128, MTOT / 128), blk, GEMM_SMEM>>>(
        oh, nullptr, woh, bo, nullptr, nullptr, out, MTOT, HID, HID);
}

// round 12
// speedup vs baseline: 2.4737x; 1.2480x over previous
#include <cuda_runtime.h>
#include <cuda_fp16.h>
#include <cstdint>

#define BATCH 2
#define SEQ   2048
#define HID   2048
#define NH    32
#define NG    8
#define HD    64
#define KVD   (NG*HD)     // 512
#define MTOT  (BATCH*SEQ) // 4096
#define NC    (HID + 2*KVD)  // 3072 combined QKV cols

typedef __half fp16;

// ---------------- device scratch (no allocation allowed) ----------------
__device__ fp16 g_xh[(size_t)MTOT*HID];                           // hi only
__device__ fp16 g_wch[(size_t)HID*NC];                            // [K, Q|K|V] hi only
__device__ fp16 g_woh[(size_t)HID*HID];                           // [K,N] hi only
__device__ fp16 g_qh[(size_t)BATCH*NH*SEQ*HD];                    // hi only
__device__ fp16 g_kh[(size_t)BATCH*NG*SEQ*HD];                    // hi only
__device__ fp16 g_vh[(size_t)BATCH*NG*HD*SEQ];                    // [b,g,d,s] hi only
__device__ fp16 g_oh[(size_t)MTOT*HID];                           // hi only

// ---------------- helpers ----------------
__device__ __forceinline__ uint32_t pack2h(float x0, float x1) {
    __half2 hb = __floats2half2_rn(x0, x1);
    return *reinterpret_cast<uint32_t*>(&hb);
}

__device__ __forceinline__ void mma_f16(float d[4], const uint32_t a[4],
                                        uint32_t b0, uint32_t b1) {
    asm volatile(
        "mma.sync.aligned.m16n8k16.row.col.f32.f16.f16.f32 "
        "{%0,%1,%2,%3}, {%4,%5,%6,%7}, {%8,%9}, {%0,%1,%2,%3};\n"
        : "+f"(d[0]), "+f"(d[1]), "+f"(d[2]), "+f"(d[3])
        : "r"(a[0]), "r"(a[1]), "r"(a[2]), "r"(a[3]), "r"(b0), "r"(b1));
}

__device__ __forceinline__ void ldsm4(uint32_t& r0, uint32_t& r1, uint32_t& r2,
                                      uint32_t& r3, uint32_t addr) {
    asm volatile("ldmatrix.sync.aligned.m8n8.x4.shared.b16 {%0,%1,%2,%3}, [%4];"
                 : "=r"(r0), "=r"(r1), "=r"(r2), "=r"(r3) : "r"(addr));
}
__device__ __forceinline__ void ldsm4t(uint32_t& r0, uint32_t& r1, uint32_t& r2,
                                       uint32_t& r3, uint32_t addr) {
    asm volatile("ldmatrix.sync.aligned.m8n8.x4.trans.shared.b16 {%0,%1,%2,%3}, [%4];"
                 : "=r"(r0), "=r"(r1), "=r"(r2), "=r"(r3) : "r"(addr));
}

__device__ __forceinline__ void cp16(uint32_t saddr, const void* gaddr) {
    asm volatile("cp.async.cg.shared.global [%0], [%1], 16;"
                 :: "r"(saddr), "l"(gaddr) : "memory");
}
#define CP_COMMIT() asm volatile("cp.async.commit_group;" ::: "memory")
#define CP_WAIT0()  asm volatile("cp.async.wait_group 0;"  ::: "memory")

// ---------------- fp32 -> fp16 converts ----------------
__global__ __launch_bounds__(256) void convert_h_kernel(
    const float* __restrict__ src, fp16* __restrict__ h, int n4)
{
    const int i = blockIdx.x * blockDim.x + threadIdx.x;
    if (i >= n4) return;
    float4 v = reinterpret_cast<const float4*>(src)[i];
    reinterpret_cast<uint32_t*>(h)[i * 2]     = pack2h(v.x, v.y);
    reinterpret_cast<uint32_t*>(h)[i * 2 + 1] = pack2h(v.z, v.w);
}

// W [2048, Nsrc] fp32 -> combined [2048, NC] fp16 hi at column offset
__global__ __launch_bounds__(256) void convW_kernel(
    const float* __restrict__ src, fp16* __restrict__ h, int Nsrc, int colOff, int n4)
{
    const int i = blockIdx.x * blockDim.x + threadIdx.x;
    if (i >= n4) return;
    const int perRow = Nsrc >> 2;
    const int k = i / perRow;
    const int c4 = (i - k * perRow) * 4;
    float4 v = reinterpret_cast<const float4*>(src)[i];
    const size_t o = ((size_t)k * NC + colOff + c4) >> 1;  // uint32 index
    reinterpret_cast<uint32_t*>(h)[o]     = pack2h(v.x, v.y);
    reinterpret_cast<uint32_t*>(h)[o + 1] = pack2h(v.z, v.w);
}

// ---------------------------------------------------------------------------
// 1-term fp16 GEMM: C = Ah @ Bh + bias. CTA 128x128, BK=32, 256 threads
// (8 warps 4x2, warp tile 32x64), cp.async double buffer + ldmatrix.
// MODE 0: fp32 +bias -> Cf (O projection)
// MODE 4: combined QKV epilogue: Q -> hi [b,h,s,d]; K -> hi [b,g,s,d]
//         scaled by 0.125*log2e; V -> hi transposed [b,g,d,s]
// ---------------------------------------------------------------------------
#define GAP 40     // A smem pitch (fp16): 32 k + 8 pad
#define GBP 136    // B smem pitch (fp16): 128 n + 8 pad
#define GA_BYTES (128 * GAP * 2)            // 10240
#define GB_BYTES (32 * GBP * 2)             // 8704
#define GSTAGE   (GA_BYTES + GB_BYTES)      // 18944
#define GEMM_SMEM (2 * GSTAGE)              // 37888
#define KSCALE (0.125f * 1.44269504088896f)

template<int MODE>
__global__ __launch_bounds__(256, 2) void gemm_kernel(
    const fp16* __restrict__ Ah, const fp16* __restrict__ Bh,
    const float* __restrict__ bias0, const float* __restrict__ bias1,
    const float* __restrict__ bias2,
    float* __restrict__ Cf, int M, int N, int K)
{
    extern __shared__ char smc[];
    const uint32_t sbase = (uint32_t)__cvta_generic_to_shared(smc);

    const int tid  = threadIdx.x;
    const int lane = tid & 31;
    const int wid  = tid >> 5;
    const int g = lane >> 2, c = lane & 3;
    const int quad = lane >> 3, r8 = lane & 7;
    const int wm0 = (wid & 3) * 32;
    const int wn0 = (wid >> 2) * 64;
    const int row0 = blockIdx.y * 128;
    const int col0 = blockIdx.x * 128;

    float acc[2][8][4];
    #pragma unroll
    for (int mt = 0; mt < 2; mt++)
        #pragma unroll
        for (int nt = 0; nt < 8; nt++)
            #pragma unroll
            for (int j = 0; j < 4; j++) acc[mt][nt][j] = 0.0f;

    const int NT = K / 32;

    auto fill = [&](int kt, int st) {
        const int k0 = kt * 32;
        const uint32_t s0 = sbase + st * GSTAGE;
        // A: 128 rows x 32 k (512 f4, 2 per thread)
        #pragma unroll
        for (int i = 0; i < 2; i++) {
            const int idx = tid + i * 256;
            const int r = idx >> 2, q = (idx & 3) * 8;
            const size_t go = (size_t)(row0 + r) * K + k0 + q;
            cp16(s0 + (r * GAP + q) * 2, Ah + go);
        }
        // B: 32 k-rows x 128 n (512 f4, 2 per thread)
        #pragma unroll
        for (int i = 0; i < 2; i++) {
            const int idx = tid + i * 256;
            const int r = idx >> 4, q = (idx & 15) * 8;
            const size_t go = (size_t)(k0 + r) * N + col0 + q;
            cp16(s0 + GA_BYTES + (r * GBP + q) * 2, Bh + go);
        }
    };

    fill(0, 0); CP_COMMIT();

    const int arow = (quad & 1) * 8 + r8;
    const int acol = (quad >> 1) * 8;

    for (int kt = 0; kt < NT; kt++) {
        CP_WAIT0();
        __syncthreads();
        if (kt + 1 < NT) { fill(kt + 1, (kt + 1) & 1); CP_COMMIT(); }
        const uint32_t s0 = sbase + (kt & 1) * GSTAGE;

        #pragma unroll
        for (int kk = 0; kk < 2; kk++) {
            uint32_t ah[2][4];
            #pragma unroll
            for (int mt = 0; mt < 2; mt++) {
                const uint32_t aaddr =
                    s0 + ((wm0 + mt * 16 + arow) * GAP + kk * 16 + acol) * 2;
                ldsm4(ah[mt][0], ah[mt][1], ah[mt][2], ah[mt][3], aaddr);
            }
            #pragma unroll
            for (int np = 0; np < 4; np++) {
                const uint32_t baddr = s0 + GA_BYTES +
                    ((kk * 16 + arow) * GBP + wn0 + np * 16 + acol) * 2;
                uint32_t bh0, bh1, bh2, bh3;
                ldsm4t(bh0, bh1, bh2, bh3, baddr);
                #pragma unroll
                for (int mt = 0; mt < 2; mt++) {
                    mma_f16(acc[mt][2*np],   ah[mt], bh0, bh1);
                    mma_f16(acc[mt][2*np+1], ah[mt], bh2, bh3);
                }
            }
        }
    }

    // ---- epilogue ----
    #pragma unroll
    for (int mt = 0; mt < 2; mt++) {
        const int r = row0 + wm0 + mt * 16 + g;     // and r+8
        const int b0 = r >> 11, s0i = r & 2047;
        const int b1 = (r + 8) >> 11, s1i = (r + 8) & 2047;
        #pragma unroll
        for (int nt = 0; nt < 8; nt++) {
            const int n = col0 + wn0 + nt * 8 + 2 * c;
            if (MODE == 0) {
                const float bv0 = bias0[n], bv1 = bias0[n + 1];
                const float v0 = acc[mt][nt][0] + bv0;
                const float v1 = acc[mt][nt][1] + bv1;
                const float v2 = acc[mt][nt][2] + bv0;
                const float v3 = acc[mt][nt][3] + bv1;
                *(float2*)(Cf + (size_t)r * N + n)       = make_float2(v0, v1);
                *(float2*)(Cf + (size_t)(r + 8) * N + n) = make_float2(v2, v3);
            } else {
                if (n < HID) {               // ---- Q: hi [b,h,s,d] ----
                    const float bv0 = bias0[n], bv1 = bias0[n + 1];
                    const int hh = n >> 6, d = n & 63;
                    size_t o0 = (((size_t)(b0 * NH + hh)) * SEQ + s0i) * HD + d;
                    size_t o1 = (((size_t)(b1 * NH + hh)) * SEQ + s1i) * HD + d;
                    *reinterpret_cast<uint32_t*>(g_qh + o0) =
                        pack2h(acc[mt][nt][0] + bv0, acc[mt][nt][1] + bv1);
                    *reinterpret_cast<uint32_t*>(g_qh + o1) =
                        pack2h(acc[mt][nt][2] + bv0, acc[mt][nt][3] + bv1);
                } else if (n < HID + KVD) {  // ---- K: hi [b,g,s,d], xKSCALE ----
                    const int nn = n - HID;
                    const float bv0 = bias1[nn], bv1 = bias1[nn + 1];
                    const float v0 = (acc[mt][nt][0] + bv0) * KSCALE;
                    const float v1 = (acc[mt][nt][1] + bv1) * KSCALE;
                    const float v2 = (acc[mt][nt][2] + bv0) * KSCALE;
                    const float v3 = (acc[mt][nt][3] + bv1) * KSCALE;
                    const int gg = nn >> 6, d = nn & 63;
                    size_t o0 = (((size_t)(b0 * NG + gg)) * SEQ + s0i) * HD + d;
                    size_t o1 = (((size_t)(b1 * NG + gg)) * SEQ + s1i) * HD + d;
                    *reinterpret_cast<uint32_t*>(g_kh + o0) = pack2h(v0, v1);
                    *reinterpret_cast<uint32_t*>(g_kh + o1) = pack2h(v2, v3);
                } else {                     // ---- V: hi transposed [b,g,d,s] ----
                    const int nn = n - HID - KVD;
                    const float bv0 = bias2[nn], bv1 = bias2[nn + 1];
                    const float vals[4] = {
                        acc[mt][nt][0] + bv0, acc[mt][nt][1] + bv1,
                        acc[mt][nt][2] + bv0, acc[mt][nt][3] + bv1 };
                    const int gg = nn >> 6, d = nn & 63;
                    const size_t base0 = ((size_t)(b0 * NG + gg)) * HD;
                    const size_t base1 = ((size_t)(b1 * NG + gg)) * HD;
                    const size_t offs[4] = {
                        (base0 + d) * SEQ + s0i, (base0 + d + 1) * SEQ + s0i,
                        (base1 + d) * SEQ + s1i, (base1 + d + 1) * SEQ + s1i };
                    #pragma unroll
                    for (int j = 0; j < 4; j++)
                        g_vh[offs[j]] = __float2half_rn(vals[j]);
                }
            }
        }
    }
}

// ---------------------------------------------------------------------------
// Flash attention (unchanged from R11): 1-term fp16 QK + 1-term PV, K/V
// hi-only in smem, exp2 softmax. Block = (b, h, 128-query tile), 256 threads.
// ---------------------------------------------------------------------------
#define AKP 72
#define AK_BYTES (64 * AKP * 2)        // 9216
#define ASTAGE   (2 * AK_BYTES)        // 18432
#define ATTN_SMEM (2 * ASTAGE)         // 36864

__global__ __launch_bounds__(256, 2) void attn_kernel(
    const fp16* __restrict__ Qh, const fp16* __restrict__ Kh,
    const fp16* __restrict__ Vh, fp16* __restrict__ Oh)
{
    extern __shared__ char smc[];
    const uint32_t sbase = (uint32_t)__cvta_generic_to_shared(smc);

    const int tid  = threadIdx.x;
    const int lane = tid & 31;
    const int wid  = tid >> 5;
    const int g = lane >> 2, c = lane & 3;
    const int quad = lane >> 3, r8 = lane & 7;
    const int wr0 = wid * 16;
    const int lrow = (quad >> 1) * 8 + r8;
    const int lcol = (quad & 1) * 8;

    const int qt = blockIdx.x;
    const int h  = blockIdx.y;
    const int b  = blockIdx.z;
    const int gh = h >> 2;

    const size_t koff = ((size_t)(b * NG + gh)) * SEQ * HD;
    const size_t voff = ((size_t)(b * NG + gh)) * HD * SEQ;

    const fp16* qbh = Qh + (((size_t)(b * NH + h)) * SEQ + qt * 128 + wr0) * HD;
    uint32_t qh[4][4];
    #pragma unroll
    for (int kt = 0; kt < 4; kt++) {
        const int o0 = g * HD + kt * 16 + 2 * c;
        qh[kt][0] = *(const uint32_t*)(qbh + o0);
        qh[kt][1] = *(const uint32_t*)(qbh + o0 + 8 * HD);
        qh[kt][2] = *(const uint32_t*)(qbh + o0 + 8);
        qh[kt][3] = *(const uint32_t*)(qbh + o0 + 8 * HD + 8);
    }

    auto fill = [&](int t, int st) {
        const uint32_t s0 = sbase + st * ASTAGE;
        #pragma unroll
        for (int i = 0; i < 2; i++) {
            const int idx = tid + i * 256;
            const int r = idx >> 3, q = (idx & 7) * 8;
            const uint32_t so = (r * AKP + q) * 2;
            const size_t gk = koff + (size_t)(t * 64 + r) * HD + q;
            cp16(s0 + so, Kh + gk);
            const size_t gv = voff + (size_t)r * SEQ + t * 64 + q;
            cp16(s0 + AK_BYTES + so, Vh + gv);
        }
    };

    float m0 = -1e30f, m1 = -1e30f, l0 = 0.0f, l1 = 0.0f;
    float oacc[8][4];
    #pragma unroll
    for (int nt = 0; nt < 8; nt++)
        #pragma unroll
        for (int j = 0; j < 4; j++) oacc[nt][j] = 0.0f;

    fill(0, 0); CP_COMMIT();

    for (int t = 0; t < SEQ / 64; t++) {
        CP_WAIT0();
        __syncthreads();
        if (t + 1 < SEQ / 64) { fill(t + 1, (t + 1) & 1); CP_COMMIT(); }
        const uint32_t sK = sbase + (t & 1) * ASTAGE;
        const uint32_t sV = sK + AK_BYTES;

        // ---- S = Q @ K^T (1-term fp16) ----
        float sv[8][4];
        #pragma unroll
        for (int nt = 0; nt < 8; nt++)
            #pragma unroll
            for (int j = 0; j < 4; j++) sv[nt][j] = 0.0f;

        #pragma unroll
        for (int np = 0; np < 4; np++) {
            #pragma unroll
            for (int kt = 0; kt < 4; kt++) {
                const uint32_t ka = sK + ((np * 16 + lrow) * AKP + kt * 16 + lcol) * 2;
                uint32_t h0, h1, h2, h3;
                ldsm4(h0, h1, h2, h3, ka);
                mma_f16(sv[2*np],   qh[kt], h0, h1);
                mma_f16(sv[2*np+1], qh[kt], h2, h3);
            }
        }

        // ---- online softmax (exp2; log2e folded into K) ----
        float mx0 = -1e30f, mx1 = -1e30f;
        #pragma unroll
        for (int nt = 0; nt < 8; nt++) {
            mx0 = fmaxf(mx0, fmaxf(sv[nt][0], sv[nt][1]));
            mx1 = fmaxf(mx1, fmaxf(sv[nt][2], sv[nt][3]));
        }
        mx0 = fmaxf(mx0, __shfl_xor_sync(0xffffffffu, mx0, 1));
        mx0 = fmaxf(mx0, __shfl_xor_sync(0xffffffffu, mx0, 2));
        mx1 = fmaxf(mx1, __shfl_xor_sync(0xffffffffu, mx1, 1));
        mx1 = fmaxf(mx1, __shfl_xor_sync(0xffffffffu, mx1, 2));

        const float nm0 = fmaxf(m0, mx0), nm1 = fmaxf(m1, mx1);
        const float corr0 = exp2f(m0 - nm0), corr1 = exp2f(m1 - nm1);
        float ls0 = 0.0f, ls1 = 0.0f;
        #pragma unroll
        for (int nt = 0; nt < 8; nt++) {
            sv[nt][0] = exp2f(sv[nt][0] - nm0);
            sv[nt][1] = exp2f(sv[nt][1] - nm0);
            sv[nt][2] = exp2f(sv[nt][2] - nm1);
            sv[nt][3] = exp2f(sv[nt][3] - nm1);
            ls0 += sv[nt][0] + sv[nt][1];
            ls1 += sv[nt][2] + sv[nt][3];
        }
        ls0 += __shfl_xor_sync(0xffffffffu, ls0, 1);
        ls0 += __shfl_xor_sync(0xffffffffu, ls0, 2);
        ls1 += __shfl_xor_sync(0xffffffffu, ls1, 1);
        ls1 += __shfl_xor_sync(0xffffffffu, ls1, 2);
        l0 = l0 * corr0 + ls0; m0 = nm0;
        l1 = l1 * corr1 + ls1; m1 = nm1;
        #pragma unroll
        for (int nt = 0; nt < 8; nt++) {
            oacc[nt][0] *= corr0; oacc[nt][1] *= corr0;
            oacc[nt][2] *= corr1; oacc[nt][3] *= corr1;
        }

        // ---- O += P @ V (P packed fp16, 1-term; V hi in smem) ----
        #pragma unroll
        for (int kt = 0; kt < 4; kt++) {
            uint32_t ph[4];
            ph[0] = pack2h(sv[2*kt][0],   sv[2*kt][1]);
            ph[1] = pack2h(sv[2*kt][2],   sv[2*kt][3]);
            ph[2] = pack2h(sv[2*kt+1][0], sv[2*kt+1][1]);
            ph[3] = pack2h(sv[2*kt+1][2], sv[2*kt+1][3]);
            #pragma unroll
            for (int np = 0; np < 4; np++) {
                const uint32_t va = sV + ((np * 16 + lrow) * AKP + kt * 16 + lcol) * 2;
                uint32_t h0, h1, h2, h3;
                ldsm4(h0, h1, h2, h3, va);
                mma_f16(oacc[2*np],   ph, h0, h1);
                mma_f16(oacc[2*np+1], ph, h2, h3);
            }
        }
    }

    // ---- epilogue: normalize, store fp16 hi to [b,s,h*64+d] ----
    const float inv0 = 1.0f / l0, inv1 = 1.0f / l1;
    const int s0 = qt * 128 + wr0 + g;
    const size_t ob0 = ((size_t)b * SEQ + s0) * HID + h * HD;
    const size_t ob1 = ((size_t)b * SEQ + s0 + 8) * HID + h * HD;
    #pragma unroll
    for (int nt = 0; nt < 8; nt++) {
        const int d = nt * 8 + 2 * c;
        *reinterpret_cast<uint32_t*>(Oh + ob0 + d) =
            pack2h(oacc[nt][0] * inv0, oacc[nt][1] * inv0);
        *reinterpret_cast<uint32_t*>(Oh + ob1 + d) =
            pack2h(oacc[nt][2] * inv1, oacc[nt][3] * inv1);
    }
}

// ---------------------------------------------------------------------------
extern "C" void kernel_launch(void* const* d_in, const int* in_sizes, int n_in,
                              void* d_out, int out_size)
{
    const float* X  = (const float*)d_in[0];
    const float* Wq = (const float*)d_in[1];
    const float* bq = (const float*)d_in[2];
    const float* Wk = (const float*)d_in[3];
    const float* bk = (const float*)d_in[4];
    const float* Wv = (const float*)d_in[5];
    const float* bv = (const float*)d_in[6];
    const float* Wo = (const float*)d_in[7];
    const float* bo = (const float*)d_in[8];
    float* out = (float*)d_out;

    fp16 *xh, *wch, *woh, *qh, *kh, *vh, *oh;
    cudaGetSymbolAddress((void**)&xh,  g_xh);
    cudaGetSymbolAddress((void**)&wch, g_wch); cudaGetSymbolAddress((void**)&woh, g_woh);
    cudaGetSymbolAddress((void**)&qh,  g_qh);
    cudaGetSymbolAddress((void**)&kh,  g_kh);  cudaGetSymbolAddress((void**)&vh,  g_vh);
    cudaGetSymbolAddress((void**)&oh,  g_oh);

    cudaFuncSetAttribute(gemm_kernel<0>, cudaFuncAttributeMaxDynamicSharedMemorySize, GEMM_SMEM);
    cudaFuncSetAttribute(gemm_kernel<4>, cudaFuncAttributeMaxDynamicSharedMemorySize, GEMM_SMEM);
    cudaFuncSetAttribute(attn_kernel, cudaFuncAttributeMaxDynamicSharedMemorySize, ATTN_SMEM);

    // ---- converts (all hi-only) ----
    {
        const int n4 = MTOT * HID / 4;
        convert_h_kernel<<<(n4 + 255) / 256, 256>>>(X, xh, n4);
    }
    {   // Wq/Wk/Wv -> combined [2048, 3072] hi only
        int n4q = HID * HID / 4;
        convW_kernel<<<(n4q + 255) / 256, 256>>>(Wq, wch, HID, 0, n4q);
        int n4k = HID * KVD / 4;
        convW_kernel<<<(n4k + 255) / 256, 256>>>(Wk, wch, KVD, HID, n4k);
        convW_kernel<<<(n4k + 255) / 256, 256>>>(Wv, wch, KVD, HID + KVD, n4k);
    }
    {
        const int n4 = HID * HID / 4;
        convert_h_kernel<<<(n4 + 255) / 256, 256>>>(Wo, woh, n4);
    }

    dim3 blk(256);
    // Fused QKV projection (1-term): [4096,2048] @ [2048,3072]
    gemm_kernel<4><<<dim3(NC / 128, MTOT / 128), blk, GEMM_SMEM>>>(
        xh, wch, bq, bk, bv, nullptr, MTOT, NC, HID);
    // Attention -> fp16 hi [b,s,h*d]
    attn_kernel<<<dim3(SEQ / 128, NH, BATCH), blk, ATTN_SMEM>>>(
        qh, kh, vh, oh);
    // Output projection (1-term) -> fp32 d_out
    gemm_kernel<0><<<dim3(HID / 128, MTOT / 128), blk, GEMM_SMEM>>>(
        oh, woh, bo, nullptr, nullptr, out, MTOT, HID, HID);
}